// round 9
// baseline (speedup 1.0000x reference)
#include <cuda_runtime.h>
#include <cuda_bf16.h>
#include <cuda_fp16.h>
#include <math.h>
#include <cstdint>

#define IN_FEATS 256
#define HIDDEN   128
#define OUT_FEATS 64
#define MAX_NODES 50048
#define MAX_EDGES 800000
#define SCAN_BLK  256

// ---------------- scratch (static device globals) --------------------------
__device__ int   g_degi_out[MAX_NODES];
__device__ int   g_degi_in[MAX_NODES];
__device__ float g_ns[MAX_NODES];
__device__ float g_nd[MAX_NODES];
__device__ int   g_row_ptr[MAX_NODES];
__device__ int   g_cursor[MAX_NODES];
__device__ int   g_sorted_src[MAX_EDGES];
__device__ int   g_bsum[(MAX_NODES + SCAN_BLK - 1) / SCAN_BLK];
__device__ int   g_bpre[(MAX_NODES + SCAN_BLK - 1) / SCAN_BLK];
__device__ __align__(16) __half g_m1[(size_t)MAX_NODES * HIDDEN];
__device__ __align__(16) __half g_m2[(size_t)MAX_NODES * OUT_FEATS];
// W images: [N rows][K+8 cols] bf16, hi/lo split, 16B-aligned
__device__ __align__(16) __nv_bfloat16 g_w1hi[HIDDEN * (IN_FEATS + 8)];
__device__ __align__(16) __nv_bfloat16 g_w1lo[HIDDEN * (IN_FEATS + 8)];
__device__ __align__(16) __nv_bfloat16 g_w2hi[OUT_FEATS * (HIDDEN + 8)];
__device__ __align__(16) __nv_bfloat16 g_w2lo[OUT_FEATS * (HIDDEN + 8)];
__device__ int   g_is64;

// ---------------- PTX helpers ----------------------------------------------
__device__ __forceinline__ uint32_t smem_u32(const void* p) {
    uint32_t a;
    asm("{ .reg .u64 t; cvta.to.shared.u64 t, %1; cvt.u32.u64 %0, t; }" : "=r"(a) : "l"(p));
    return a;
}

#define LDM_X4(r, a) \
    asm volatile("ldmatrix.sync.aligned.m8n8.x4.shared.b16 {%0,%1,%2,%3}, [%4];" \
        : "=r"((r)[0]), "=r"((r)[1]), "=r"((r)[2]), "=r"((r)[3]) : "r"(a))

#define MMA_BF16(d, a, b) \
    asm volatile("mma.sync.aligned.m16n8k16.row.col.f32.bf16.bf16.f32 " \
        "{%0,%1,%2,%3}, {%4,%5,%6,%7}, {%8,%9}, {%0,%1,%2,%3};" \
        : "+f"((d)[0]), "+f"((d)[1]), "+f"((d)[2]), "+f"((d)[3]) \
        : "r"((a)[0]), "r"((a)[1]), "r"((a)[2]), "r"((a)[3]), \
          "r"((b)[0]), "r"((b)[1]))

__device__ __forceinline__ void split_bf16(float v, unsigned short& h, unsigned short& l) {
    __nv_bfloat16 hb = __float2bfloat16(v);
    __nv_bfloat16 lb = __float2bfloat16(v - __bfloat162float(hb));
    h = *(unsigned short*)&hb;
    l = *(unsigned short*)&lb;
}

// ---------------- index dtype detector ------------------------------------
__global__ void detect_i64_kernel(const unsigned int* __restrict__ words, int E) {
    int is64 = 1;
    int nchk = E < 32 ? E : 32;
    for (int i = 0; i < nchk; i++) {
        if (words[2 * i + 1] != 0u) { is64 = 0; break; }
    }
    g_is64 = is64;
}

__device__ __forceinline__ int load_idx(const void* p, int i) {
    if (g_is64) return (int)((const long long*)p)[i];
    return ((const int*)p)[i];
}

// ---------------- degrees (8 edges/thread, loads hoisted) ------------------
__global__ void degree_kernel(const void* __restrict__ src, const void* __restrict__ dst, int E) {
    int e0 = (blockIdx.x * blockDim.x + threadIdx.x) * 8;
    int s[8], d[8];
    #pragma unroll
    for (int i = 0; i < 8; i++) {
        int e = e0 + i;
        if (e < E) { s[i] = load_idx(src, e); d[i] = load_idx(dst, e); }
        else { s[i] = -1; d[i] = -1; }
    }
    #pragma unroll
    for (int i = 0; i < 8; i++) {
        if (s[i] >= 0) {
            atomicAdd(&g_degi_out[s[i]], 1);
            atomicAdd(&g_degi_in[d[i]], 1);
        }
    }
}

// ---------------- exclusive scan of g_degi_in -> g_row_ptr -----------------
__global__ void scan_block_sums(int N) {
    __shared__ int sm[SCAN_BLK];
    int i = blockIdx.x * SCAN_BLK + threadIdx.x;
    int v = (i < N) ? g_degi_in[i] : 0;
    sm[threadIdx.x] = v;
    __syncthreads();
    for (int s = SCAN_BLK / 2; s > 0; s >>= 1) {
        if (threadIdx.x < s) sm[threadIdx.x] += sm[threadIdx.x + s];
        __syncthreads();
    }
    if (threadIdx.x == 0) g_bsum[blockIdx.x] = sm[0];
}

// single-block parallel exclusive scan over block sums (nb <= 256)
__global__ void scan_partials(int nb) {
    __shared__ int sm[SCAN_BLK];
    int v = (threadIdx.x < nb) ? g_bsum[threadIdx.x] : 0;
    sm[threadIdx.x] = v;
    __syncthreads();
    for (int off = 1; off < SCAN_BLK; off <<= 1) {
        int t = (threadIdx.x >= off) ? sm[threadIdx.x - off] : 0;
        __syncthreads();
        sm[threadIdx.x] += t;
        __syncthreads();
    }
    if (threadIdx.x < nb) g_bpre[threadIdx.x] = sm[threadIdx.x] - v;
}

// scan_final also computes norms and zeroes the cursor (fused)
__global__ void scan_final(int N) {
    __shared__ int sm[SCAN_BLK];
    int i = blockIdx.x * SCAN_BLK + threadIdx.x;
    int v = (i < N) ? g_degi_in[i] : 0;
    sm[threadIdx.x] = v;
    __syncthreads();
    for (int off = 1; off < SCAN_BLK; off <<= 1) {
        int t = (threadIdx.x >= off) ? sm[threadIdx.x - off] : 0;
        __syncthreads();
        sm[threadIdx.x] += t;
        __syncthreads();
    }
    if (i < N) {
        g_row_ptr[i] = g_bpre[blockIdx.x] + sm[threadIdx.x] - v;
        g_cursor[i] = 0;
        g_ns[i] = rsqrtf(fmaxf((float)g_degi_out[i], 1.0f));
        g_nd[i] = rsqrtf(fmaxf((float)v, 1.0f));
    }
}

// ---------------- counting-sort fill (4 edges/thread) ----------------------
__global__ void fill_csr_kernel(const void* __restrict__ src, const void* __restrict__ dst, int E) {
    int e0 = (blockIdx.x * blockDim.x + threadIdx.x) * 4;
    int s[4], d[4];
    #pragma unroll
    for (int i = 0; i < 4; i++) {
        int e = e0 + i;
        if (e < E) { s[i] = load_idx(src, e); d[i] = load_idx(dst, e); }
        else { s[i] = -1; d[i] = -1; }
    }
    #pragma unroll
    for (int i = 0; i < 4; i++) {
        if (s[i] >= 0) {
            int pos = g_row_ptr[d[i]] + atomicAdd(&g_cursor[d[i]], 1);
            g_sorted_src[pos] = s[i];
        }
    }
}

// ---------------- W prep: split fp32 W[K,N] -> bf16 hi/lo [N][K+8] images --
template <int K, int N>
__global__ void wprep_kernel(const float* __restrict__ W,
                             __nv_bfloat16* __restrict__ hi,
                             __nv_bfloat16* __restrict__ lo) {
    int idx = blockIdx.x * blockDim.x + threadIdx.x;
    if (idx >= K * N) return;
    int n = idx / K;
    int k = idx - n * K;
    float v = W[(size_t)k * N + n];
    unsigned short h, l;
    split_bf16(v, h, l);
    hi[n * (K + 8) + k] = *(__nv_bfloat16*)&h;
    lo[n * (K + 8) + k] = *(__nv_bfloat16*)&l;
}

// ---------------- GEMM1: m1(fp16) = (x*ns) @ W1  (bf16-split mma.sync) -----
__global__ __launch_bounds__(256) void gemm1_kernel(
    const float* __restrict__ A,
    const __nv_bfloat16* __restrict__ Whi, const __nv_bfloat16* __restrict__ Wlo,
    __half* __restrict__ C, const float* __restrict__ ns, int M)
{
    constexpr int N = HIDDEN, KTOT = IN_FEATS;
    constexpr int BK = 64, BKP = BK + 8, KP = KTOT + 8;
    constexpr int TN_W = N / 2;          // 64
    constexpr int NFR = TN_W / 8;        // 8
    constexpr int WB = N * KP;

    extern __shared__ __nv_bfloat16 smbuf[];
    __nv_bfloat16* Wh = smbuf;
    __nv_bfloat16* Wl = smbuf + WB;
    __nv_bfloat16* Ah = smbuf + 2 * (size_t)WB;
    __nv_bfloat16* Al = Ah + 128 * BKP;

    const int tid = threadIdx.x, lane = tid & 31, wid = tid >> 5;
    const int wm = wid & 3, wn = wid >> 2;
    const int row0 = blockIdx.x * 128;

    {
        const float4* s1 = (const float4*)Whi;
        const float4* s2 = (const float4*)Wlo;
        float4* d1 = (float4*)Wh;
        float4* d2 = (float4*)Wl;
        #pragma unroll 4
        for (int i = tid; i < WB / 8; i += 256) { d1[i] = s1[i]; d2[i] = s2[i]; }
    }

    float acc[2][NFR][4] = {};

    const int a_row = (lane & 7) + ((lane >> 3) & 1) * 8;
    const int a_col = (lane >> 4) * 8;
    const int b_row = (lane & 7) + (lane >> 4) * 8;
    const int b_col = ((lane >> 3) & 1) * 8;

    for (int c = 0; c < KTOT / BK; c++) {
        __syncthreads();
        #pragma unroll
        for (int l = 0; l < 8; l++) {
            int idx = tid + l * 256;
            int m = idx >> 4, k4 = idx & 15;
            int gm = row0 + m;
            float4 v = make_float4(0.f, 0.f, 0.f, 0.f);
            if (gm < M) {
                v = *(const float4*)(A + (size_t)gm * KTOT + c * BK + k4 * 4);
                float s = ns[gm];
                v.x *= s; v.y *= s; v.z *= s; v.w *= s;
            }
            ushort4 h4, l4;
            split_bf16(v.x, h4.x, l4.x);
            split_bf16(v.y, h4.y, l4.y);
            split_bf16(v.z, h4.z, l4.z);
            split_bf16(v.w, h4.w, l4.w);
            *(ushort4*)(Ah + m * BKP + k4 * 4) = h4;
            *(ushort4*)(Al + m * BKP + k4 * 4) = l4;
        }
        __syncthreads();

        #pragma unroll
        for (int k16 = 0; k16 < BK / 16; k16++) {
            int kc = k16 * 16;
            int kg = c * BK + kc;
            uint32_t ah[2][4], al[2][4];
            #pragma unroll
            for (int mi = 0; mi < 2; mi++) {
                int ar = wm * 32 + mi * 16 + a_row;
                LDM_X4(ah[mi], smem_u32(Ah + ar * BKP + kc + a_col));
                LDM_X4(al[mi], smem_u32(Al + ar * BKP + kc + a_col));
            }
            #pragma unroll
            for (int ng = 0; ng < NFR / 2; ng++) {
                int n0 = wn * TN_W + ng * 16;
                uint32_t bh[4], bl[4];
                LDM_X4(bh, smem_u32(Wh + (n0 + b_row) * KP + kg + b_col));
                LDM_X4(bl, smem_u32(Wl + (n0 + b_row) * KP + kg + b_col));
                #pragma unroll
                for (int mi = 0; mi < 2; mi++) {
                    MMA_BF16(acc[mi][2 * ng],     ah[mi], (bh + 0));
                    MMA_BF16(acc[mi][2 * ng + 1], ah[mi], (bh + 2));
                    MMA_BF16(acc[mi][2 * ng],     ah[mi], (bl + 0));
                    MMA_BF16(acc[mi][2 * ng + 1], ah[mi], (bl + 2));
                    MMA_BF16(acc[mi][2 * ng],     al[mi], (bh + 0));
                    MMA_BF16(acc[mi][2 * ng + 1], al[mi], (bh + 2));
                }
            }
        }
    }

    #pragma unroll
    for (int mi = 0; mi < 2; mi++) {
        int r = row0 + wm * 32 + mi * 16 + (lane >> 2);
        #pragma unroll
        for (int nf = 0; nf < NFR; nf++) {
            int col = wn * TN_W + nf * 8 + (lane & 3) * 2;
            if (r < M)
                *(__half2*)(C + (size_t)r * N + col) =
                    __floats2half2_rn(acc[mi][nf][0], acc[mi][nf][1]);
            if (r + 8 < M)
                *(__half2*)(C + (size_t)(r + 8) * N + col) =
                    __floats2half2_rn(acc[mi][nf][2], acc[mi][nf][3]);
        }
    }
}

// ---------------- FUSED: gather1 + GEMM2 ------------------------------------
// Per CTA: 128 dst nodes. Warp-per-node CSR gather of fp16 m1 rows (fp32 acc),
// epilogue (acc*nd + b1 -> relu -> *ns) in registers, bf16 hi/lo split into
// smem A images, then mma with W2 -> m2 (fp16). g_agg1 eliminated.
__global__ __launch_bounds__(256) void fused_gather_gemm2_kernel(
    const __half* __restrict__ m1,
    const __nv_bfloat16* __restrict__ Whi, const __nv_bfloat16* __restrict__ Wlo,
    __half* __restrict__ C, const float* __restrict__ b1, int M)
{
    constexpr int N = OUT_FEATS, KTOT = HIDDEN;   // 64, 128
    constexpr int KP = KTOT + 8;                  // W image stride: 136
    constexpr int AKP = KTOT + 8;                 // A image stride: 136
    constexpr int TN_W = N / 2;                   // 32
    constexpr int NFR = TN_W / 8;                 // 4
    constexpr int WB = N * KP;                    // 8704

    extern __shared__ __nv_bfloat16 smbuf[];
    __nv_bfloat16* Wh = smbuf;
    __nv_bfloat16* Wl = smbuf + WB;
    __nv_bfloat16* Ah = smbuf + 2 * (size_t)WB;
    __nv_bfloat16* Al = Ah + 128 * AKP;

    const int tid = threadIdx.x, lane = tid & 31, wid = tid >> 5;
    const int wm = wid & 3, wn = wid >> 2;
    const int row0 = blockIdx.x * 128;

    {
        const float4* s1 = (const float4*)Whi;
        const float4* s2 = (const float4*)Wlo;
        float4* d1 = (float4*)Wh;
        float4* d2 = (float4*)Wl;
        #pragma unroll 4
        for (int i = tid; i < WB / 8; i += 256) { d1[i] = s1[i]; d2[i] = s2[i]; }
    }

    // ---- gather phase: warp w handles rows w, w+8, ..., w+120 ----
    for (int r = wid; r < 128; r += 8) {
        int n = row0 + r;
        float4 acc = make_float4(0.f, 0.f, 0.f, 0.f);
        float nd = 0.f, ns_ = 0.f;
        if (n < M) {
            int beg = g_row_ptr[n];
            int cnt = g_degi_in[n];
            const int* __restrict__ ss = g_sorted_src + beg;
            int e = 0;
            for (; e + 4 <= cnt; e += 4) {
                int s0 = ss[e], s1 = ss[e + 1], s2 = ss[e + 2], s3 = ss[e + 3];
                uint2 r0 = __ldg((const uint2*)(m1 + (size_t)s0 * KTOT) + lane);
                uint2 r1 = __ldg((const uint2*)(m1 + (size_t)s1 * KTOT) + lane);
                uint2 r2 = __ldg((const uint2*)(m1 + (size_t)s2 * KTOT) + lane);
                uint2 r3 = __ldg((const uint2*)(m1 + (size_t)s3 * KTOT) + lane);
                float2 a, b;
                a = __half22float2(*(__half2*)&r0.x); b = __half22float2(*(__half2*)&r0.y);
                acc.x += a.x; acc.y += a.y; acc.z += b.x; acc.w += b.y;
                a = __half22float2(*(__half2*)&r1.x); b = __half22float2(*(__half2*)&r1.y);
                acc.x += a.x; acc.y += a.y; acc.z += b.x; acc.w += b.y;
                a = __half22float2(*(__half2*)&r2.x); b = __half22float2(*(__half2*)&r2.y);
                acc.x += a.x; acc.y += a.y; acc.z += b.x; acc.w += b.y;
                a = __half22float2(*(__half2*)&r3.x); b = __half22float2(*(__half2*)&r3.y);
                acc.x += a.x; acc.y += a.y; acc.z += b.x; acc.w += b.y;
            }
            for (; e < cnt; e++) {
                uint2 r0 = __ldg((const uint2*)(m1 + (size_t)ss[e] * KTOT) + lane);
                float2 a = __half22float2(*(__half2*)&r0.x);
                float2 b = __half22float2(*(__half2*)&r0.y);
                acc.x += a.x; acc.y += a.y; acc.z += b.x; acc.w += b.y;
            }
            nd = g_nd[n];
            ns_ = g_ns[n];
        }
        float4 bb = __ldg((const float4*)b1 + lane);
        float v0 = fmaxf(acc.x * nd + bb.x, 0.f) * ns_;
        float v1 = fmaxf(acc.y * nd + bb.y, 0.f) * ns_;
        float v2 = fmaxf(acc.z * nd + bb.z, 0.f) * ns_;
        float v3 = fmaxf(acc.w * nd + bb.w, 0.f) * ns_;
        if (n >= M) { v0 = v1 = v2 = v3 = 0.f; }
        ushort4 h4, l4;
        split_bf16(v0, h4.x, l4.x);
        split_bf16(v1, h4.y, l4.y);
        split_bf16(v2, h4.z, l4.z);
        split_bf16(v3, h4.w, l4.w);
        *(ushort4*)(Ah + r * AKP + lane * 4) = h4;
        *(ushort4*)(Al + r * AKP + lane * 4) = l4;
    }
    __syncthreads();

    // ---- mma phase: K = 128, one chunk ----
    float acc[2][NFR][4] = {};
    const int a_row = (lane & 7) + ((lane >> 3) & 1) * 8;
    const int a_col = (lane >> 4) * 8;
    const int b_row = (lane & 7) + (lane >> 4) * 8;
    const int b_col = ((lane >> 3) & 1) * 8;

    #pragma unroll
    for (int k16 = 0; k16 < KTOT / 16; k16++) {
        int kg = k16 * 16;
        uint32_t ah[2][4], al[2][4];
        #pragma unroll
        for (int mi = 0; mi < 2; mi++) {
            int ar = wm * 32 + mi * 16 + a_row;
            LDM_X4(ah[mi], smem_u32(Ah + ar * AKP + kg + a_col));
            LDM_X4(al[mi], smem_u32(Al + ar * AKP + kg + a_col));
        }
        #pragma unroll
        for (int ng = 0; ng < NFR / 2; ng++) {
            int n0 = wn * TN_W + ng * 16;
            uint32_t bh[4], bl[4];
            LDM_X4(bh, smem_u32(Wh + (n0 + b_row) * KP + kg + b_col));
            LDM_X4(bl, smem_u32(Wl + (n0 + b_row) * KP + kg + b_col));
            #pragma unroll
            for (int mi = 0; mi < 2; mi++) {
                MMA_BF16(acc[mi][2 * ng],     ah[mi], (bh + 0));
                MMA_BF16(acc[mi][2 * ng + 1], ah[mi], (bh + 2));
                MMA_BF16(acc[mi][2 * ng],     ah[mi], (bl + 0));
                MMA_BF16(acc[mi][2 * ng + 1], ah[mi], (bl + 2));
                MMA_BF16(acc[mi][2 * ng],     al[mi], (bh + 0));
                MMA_BF16(acc[mi][2 * ng + 1], al[mi], (bh + 2));
            }
        }
    }

    #pragma unroll
    for (int mi = 0; mi < 2; mi++) {
        int r = row0 + wm * 32 + mi * 16 + (lane >> 2);
        #pragma unroll
        for (int nf = 0; nf < NFR; nf++) {
            int col = wn * TN_W + nf * 8 + (lane & 3) * 2;
            if (r < M)
                *(__half2*)(C + (size_t)r * N + col) =
                    __floats2half2_rn(acc[mi][nf][0], acc[mi][nf][1]);
            if (r + 8 < M)
                *(__half2*)(C + (size_t)(r + 8) * N + col) =
                    __floats2half2_rn(acc[mi][nf][2], acc[mi][nf][3]);
        }
    }
}

// ---------------- final gather: out = (sum_bucket m2[src]) * nd + b2 -------
__global__ __launch_bounds__(256) void gather2_kernel(
    const __half* __restrict__ m, float* __restrict__ agg,
    const float* __restrict__ bias, int N)
{
    constexpr int C = OUT_FEATS;
    int n    = (blockIdx.x * blockDim.x + threadIdx.x) >> 5;
    int lane = threadIdx.x & 31;
    if (n >= N) return;
    int beg = g_row_ptr[n];
    int cnt = g_degi_in[n];
    const int* __restrict__ ss = g_sorted_src + beg;

    float2 acc = make_float2(0.f, 0.f);
    int e = 0;
    for (; e + 4 <= cnt; e += 4) {
        int s0 = ss[e], s1 = ss[e + 1], s2 = ss[e + 2], s3 = ss[e + 3];
        uint32_t r0 = __ldg((const uint32_t*)(m + (size_t)s0 * C) + lane);
        uint32_t r1 = __ldg((const uint32_t*)(m + (size_t)s1 * C) + lane);
        uint32_t r2 = __ldg((const uint32_t*)(m + (size_t)s2 * C) + lane);
        uint32_t r3 = __ldg((const uint32_t*)(m + (size_t)s3 * C) + lane);
        float2 a;
        a = __half22float2(*(__half2*)&r0); acc.x += a.x; acc.y += a.y;
        a = __half22float2(*(__half2*)&r1); acc.x += a.x; acc.y += a.y;
        a = __half22float2(*(__half2*)&r2); acc.x += a.x; acc.y += a.y;
        a = __half22float2(*(__half2*)&r3); acc.x += a.x; acc.y += a.y;
    }
    for (; e < cnt; e++) {
        uint32_t r0 = __ldg((const uint32_t*)(m + (size_t)ss[e] * C) + lane);
        float2 a = __half22float2(*(__half2*)&r0);
        acc.x += a.x; acc.y += a.y;
    }
    float nd = g_nd[n];
    float2 bb = ((const float2*)bias)[lane];
    acc.x = acc.x * nd + bb.x; acc.y = acc.y * nd + bb.y;
    ((float2*)(agg + (size_t)n * C))[lane] = acc;
}

// ---------------- launch ---------------------------------------------------
extern "C" void kernel_launch(void* const* d_in, const int* in_sizes, int n_in,
                              void* d_out, int out_size) {
    const float* x  = (const float*)d_in[0];
    const void*  src = d_in[1];
    const void*  dst = d_in[2];
    const float* W1 = (const float*)d_in[3];
    const float* b1 = (const float*)d_in[4];
    const float* W2 = (const float*)d_in[5];
    const float* b2 = (const float*)d_in[6];
    float* out = (float*)d_out;

    int N = in_sizes[0] / IN_FEATS;   // 50000
    int E = in_sizes[1];              // 800000
    int nb = (N + SCAN_BLK - 1) / SCAN_BLK;

    void *p_dego, *p_degi, *p_m1, *p_m2, *p_ns;
    void *p_w1hi, *p_w1lo, *p_w2hi, *p_w2lo;
    cudaGetSymbolAddress(&p_dego, g_degi_out);
    cudaGetSymbolAddress(&p_degi, g_degi_in);
    cudaGetSymbolAddress(&p_m1,   g_m1);
    cudaGetSymbolAddress(&p_m2,   g_m2);
    cudaGetSymbolAddress(&p_ns,   g_ns);
    cudaGetSymbolAddress(&p_w1hi, g_w1hi);
    cudaGetSymbolAddress(&p_w1lo, g_w1lo);
    cudaGetSymbolAddress(&p_w2hi, g_w2hi);
    cudaGetSymbolAddress(&p_w2lo, g_w2lo);

    // smem: gemm1 = 2 W1 images + 2 A(64-chunk) images
    constexpr int SMEM1 = 2 * HIDDEN * (IN_FEATS + 8) * 2 + 2 * 128 * 72 * 2;     // 172032
    // smem: fused  = 2 W2 images + 2 A(128) images
    constexpr int SMEMF = 2 * OUT_FEATS * (HIDDEN + 8) * 2 + 2 * 128 * (HIDDEN + 8) * 2; // 104448
    cudaFuncSetAttribute(gemm1_kernel,
                         cudaFuncAttributeMaxDynamicSharedMemorySize, SMEM1);
    cudaFuncSetAttribute(fused_gather_gemm2_kernel,
                         cudaFuncAttributeMaxDynamicSharedMemorySize, SMEMF);

    cudaMemsetAsync(p_dego, 0, (size_t)N * sizeof(int));
    cudaMemsetAsync(p_degi, 0, (size_t)N * sizeof(int));

    detect_i64_kernel<<<1, 1>>>((const unsigned int*)src, E);

    wprep_kernel<IN_FEATS, HIDDEN><<<(IN_FEATS * HIDDEN + 255) / 256, 256>>>(
        W1, (__nv_bfloat16*)p_w1hi, (__nv_bfloat16*)p_w1lo);
    wprep_kernel<HIDDEN, OUT_FEATS><<<(HIDDEN * OUT_FEATS + 255) / 256, 256>>>(
        W2, (__nv_bfloat16*)p_w2hi, (__nv_bfloat16*)p_w2lo);

    degree_kernel<<<(E / 8 + 255) / 256, 256>>>(src, dst, E);

    scan_block_sums<<<nb, SCAN_BLK>>>(N);
    scan_partials<<<1, SCAN_BLK>>>(nb);
    scan_final<<<nb, SCAN_BLK>>>(N);          // row_ptr + norms + cursor=0
    fill_csr_kernel<<<(E / 4 + 255) / 256, 256>>>(src, dst, E);

    // layer 1: m1 = (x * ns) @ W1  -> fp16
    gemm1_kernel<<<(N + 127) / 128, 256, SMEM1>>>(
        x, (const __nv_bfloat16*)p_w1hi, (const __nv_bfloat16*)p_w1lo,
        (__half*)p_m1, (const float*)p_ns, N);

    // fused: gather1 + epilogue + GEMM2 -> m2 fp16
    fused_gather_gemm2_kernel<<<(N + 127) / 128, 256, SMEMF>>>(
        (const __half*)p_m1, (const __nv_bfloat16*)p_w2hi, (const __nv_bfloat16*)p_w2lo,
        (__half*)p_m2, b1, N);

    // out = (sum_bucket m2[src]) * nd + b2  (fp32)
    gather2_kernel<<<(N * 32 + 255) / 256, 256>>>(
        (const __half*)p_m2, out, b2, N);
}

// round 10
// speedup vs baseline: 1.2000x; 1.2000x over previous
#include <cuda_runtime.h>
#include <cuda_bf16.h>
#include <cuda_fp16.h>
#include <math.h>
#include <cstdint>

#define IN_FEATS 256
#define HIDDEN   128
#define OUT_FEATS 64
#define MAX_NODES 50048
#define MAX_EDGES 800000
#define SCAN_BLK  256
#define DEG_BLOCKS 112

// ---------------- scratch (static device globals) --------------------------
__device__ int   g_degi_out[MAX_NODES];
__device__ int   g_degi_in[MAX_NODES];
__device__ float g_ns[MAX_NODES];
__device__ float g_nd[MAX_NODES];
__device__ int   g_row_ptr[MAX_NODES];
__device__ int   g_cursor[MAX_NODES];
__device__ int   g_sorted_src[MAX_EDGES];
__device__ int   g_bsum[(MAX_NODES + SCAN_BLK - 1) / SCAN_BLK];
__device__ int   g_bpre[(MAX_NODES + SCAN_BLK - 1) / SCAN_BLK];
__device__ __align__(16) __half g_m1[(size_t)MAX_NODES * HIDDEN];
__device__ float g_agg1[(size_t)MAX_NODES * HIDDEN];
__device__ __align__(16) __half g_m2[(size_t)MAX_NODES * OUT_FEATS];
// W images: [N rows][K+8 cols] bf16, hi/lo split, 16B-aligned
__device__ __align__(16) __nv_bfloat16 g_w1hi[HIDDEN * (IN_FEATS + 8)];
__device__ __align__(16) __nv_bfloat16 g_w1lo[HIDDEN * (IN_FEATS + 8)];
__device__ __align__(16) __nv_bfloat16 g_w2hi[OUT_FEATS * (HIDDEN + 8)];
__device__ __align__(16) __nv_bfloat16 g_w2lo[OUT_FEATS * (HIDDEN + 8)];
__device__ int   g_is64;

// ---------------- PTX helpers ----------------------------------------------
__device__ __forceinline__ uint32_t smem_u32(const void* p) {
    uint32_t a;
    asm("{ .reg .u64 t; cvta.to.shared.u64 t, %1; cvt.u32.u64 %0, t; }" : "=r"(a) : "l"(p));
    return a;
}

#define LDM_X4(r, a) \
    asm volatile("ldmatrix.sync.aligned.m8n8.x4.shared.b16 {%0,%1,%2,%3}, [%4];" \
        : "=r"((r)[0]), "=r"((r)[1]), "=r"((r)[2]), "=r"((r)[3]) : "r"(a))

#define MMA_BF16(d, a, b) \
    asm volatile("mma.sync.aligned.m16n8k16.row.col.f32.bf16.bf16.f32 " \
        "{%0,%1,%2,%3}, {%4,%5,%6,%7}, {%8,%9}, {%0,%1,%2,%3};" \
        : "+f"((d)[0]), "+f"((d)[1]), "+f"((d)[2]), "+f"((d)[3]) \
        : "r"((a)[0]), "r"((a)[1]), "r"((a)[2]), "r"((a)[3]), \
          "r"((b)[0]), "r"((b)[1]))

__device__ __forceinline__ void split_bf16(float v, unsigned short& h, unsigned short& l) {
    __nv_bfloat16 hb = __float2bfloat16(v);
    __nv_bfloat16 lb = __float2bfloat16(v - __bfloat162float(hb));
    h = *(unsigned short*)&hb;
    l = *(unsigned short*)&lb;
}

// ---------------- index dtype detector ------------------------------------
__global__ void detect_i64_kernel(const unsigned int* __restrict__ words, int E) {
    int is64 = 1;
    int nchk = E < 32 ? E : 32;
    for (int i = 0; i < nchk; i++) {
        if (words[2 * i + 1] != 0u) { is64 = 0; break; }
    }
    g_is64 = is64;
}

__device__ __forceinline__ int load_idx(const void* p, int i) {
    if (g_is64) return (int)((const long long*)p)[i];
    return ((const int*)p)[i];
}

// ---------------- exclusive scan of g_degi_in -> g_row_ptr -----------------
__global__ void scan_block_sums(int N) {
    __shared__ int sm[SCAN_BLK];
    int i = blockIdx.x * SCAN_BLK + threadIdx.x;
    int v = (i < N) ? g_degi_in[i] : 0;
    sm[threadIdx.x] = v;
    __syncthreads();
    for (int s = SCAN_BLK / 2; s > 0; s >>= 1) {
        if (threadIdx.x < s) sm[threadIdx.x] += sm[threadIdx.x + s];
        __syncthreads();
    }
    if (threadIdx.x == 0) g_bsum[blockIdx.x] = sm[0];
}

// single-block parallel exclusive scan over block sums (nb <= 256)
__global__ void scan_partials(int nb) {
    __shared__ int sm[SCAN_BLK];
    int v = (threadIdx.x < nb) ? g_bsum[threadIdx.x] : 0;
    sm[threadIdx.x] = v;
    __syncthreads();
    for (int off = 1; off < SCAN_BLK; off <<= 1) {
        int t = (threadIdx.x >= off) ? sm[threadIdx.x - off] : 0;
        __syncthreads();
        sm[threadIdx.x] += t;
        __syncthreads();
    }
    if (threadIdx.x < nb) g_bpre[threadIdx.x] = sm[threadIdx.x] - v;
}

// scan_final also computes norms and zeroes the cursor (fused)
__global__ void scan_final(int N) {
    __shared__ int sm[SCAN_BLK];
    int i = blockIdx.x * SCAN_BLK + threadIdx.x;
    int v = (i < N) ? g_degi_in[i] : 0;
    sm[threadIdx.x] = v;
    __syncthreads();
    for (int off = 1; off < SCAN_BLK; off <<= 1) {
        int t = (threadIdx.x >= off) ? sm[threadIdx.x - off] : 0;
        __syncthreads();
        sm[threadIdx.x] += t;
        __syncthreads();
    }
    if (i < N) {
        g_row_ptr[i] = g_bpre[blockIdx.x] + sm[threadIdx.x] - v;
        g_cursor[i] = 0;
        g_ns[i] = rsqrtf(fmaxf((float)g_degi_out[i], 1.0f));
        g_nd[i] = rsqrtf(fmaxf((float)v, 1.0f));
    }
}

// ---------------- counting-sort fill (4 edges/thread) ----------------------
__global__ void fill_csr_kernel(const void* __restrict__ src, const void* __restrict__ dst, int E) {
    int e0 = (blockIdx.x * blockDim.x + threadIdx.x) * 4;
    int s[4], d[4];
    #pragma unroll
    for (int i = 0; i < 4; i++) {
        int e = e0 + i;
        if (e < E) { s[i] = load_idx(src, e); d[i] = load_idx(dst, e); }
        else { s[i] = -1; d[i] = -1; }
    }
    #pragma unroll
    for (int i = 0; i < 4; i++) {
        if (s[i] >= 0) {
            int pos = g_row_ptr[d[i]] + atomicAdd(&g_cursor[d[i]], 1);
            g_sorted_src[pos] = s[i];
        }
    }
}

// ---------------- W prep: split fp32 W[K,N] -> bf16 hi/lo [N][K+8] images --
template <int K, int N>
__global__ void wprep_kernel(const float* __restrict__ W,
                             __nv_bfloat16* __restrict__ hi,
                             __nv_bfloat16* __restrict__ lo) {
    int idx = blockIdx.x * blockDim.x + threadIdx.x;
    if (idx >= K * N) return;
    int n = idx / K;
    int k = idx - n * K;
    float v = W[(size_t)k * N + n];
    unsigned short h, l;
    split_bf16(v, h, l);
    hi[n * (K + 8) + k] = *(__nv_bfloat16*)&h;
    lo[n * (K + 8) + k] = *(__nv_bfloat16*)&l;
}

// ---------------- MEGA: gemm1 (m1 = x @ W1, unscaled) + degree counting ----
// Blocks [0, G1): 128-row GEMM tiles. Blocks [G1, G1+DEG_BLOCKS): grid-stride
// degree counting (latency-bound work packed into gemm's idle issue slots).
__global__ __launch_bounds__(256) void gemm1_deg_kernel(
    const float* __restrict__ A,
    const __nv_bfloat16* __restrict__ Whi, const __nv_bfloat16* __restrict__ Wlo,
    __half* __restrict__ C, int M, int G1,
    const void* __restrict__ src, const void* __restrict__ dst, int E)
{
    constexpr int N = HIDDEN, KTOT = IN_FEATS;
    constexpr int BK = 64, BKP = BK + 8, KP = KTOT + 8;
    constexpr int TN_W = N / 2;          // 64
    constexpr int NFR = TN_W / 8;        // 8
    constexpr int WB = N * KP;

    const int tid = threadIdx.x;

    // ---- degree-counting role ----
    if (blockIdx.x >= G1) {
        int b = blockIdx.x - G1;
        for (int e = b * 256 + tid; e < E; e += DEG_BLOCKS * 256) {
            int s = load_idx(src, e);
            int d = load_idx(dst, e);
            atomicAdd(&g_degi_out[s], 1);
            atomicAdd(&g_degi_in[d], 1);
        }
        return;
    }

    // ---- GEMM role ----
    extern __shared__ __nv_bfloat16 smbuf[];
    __nv_bfloat16* Wh = smbuf;
    __nv_bfloat16* Wl = smbuf + WB;
    __nv_bfloat16* Ah = smbuf + 2 * (size_t)WB;
    __nv_bfloat16* Al = Ah + 128 * BKP;

    const int lane = tid & 31, wid = tid >> 5;
    const int wm = wid & 3, wn = wid >> 2;
    const int row0 = blockIdx.x * 128;

    {
        const float4* s1 = (const float4*)Whi;
        const float4* s2 = (const float4*)Wlo;
        float4* d1 = (float4*)Wh;
        float4* d2 = (float4*)Wl;
        #pragma unroll 4
        for (int i = tid; i < WB / 8; i += 256) { d1[i] = s1[i]; d2[i] = s2[i]; }
    }

    float acc[2][NFR][4] = {};

    const int a_row = (lane & 7) + ((lane >> 3) & 1) * 8;
    const int a_col = (lane >> 4) * 8;
    const int b_row = (lane & 7) + (lane >> 4) * 8;
    const int b_col = ((lane >> 3) & 1) * 8;

    for (int c = 0; c < KTOT / BK; c++) {
        __syncthreads();
        #pragma unroll
        for (int l = 0; l < 8; l++) {
            int idx = tid + l * 256;
            int m = idx >> 4, k4 = idx & 15;
            int gm = row0 + m;
            float4 v = make_float4(0.f, 0.f, 0.f, 0.f);
            if (gm < M)
                v = *(const float4*)(A + (size_t)gm * KTOT + c * BK + k4 * 4);
            ushort4 h4, l4;
            split_bf16(v.x, h4.x, l4.x);
            split_bf16(v.y, h4.y, l4.y);
            split_bf16(v.z, h4.z, l4.z);
            split_bf16(v.w, h4.w, l4.w);
            *(ushort4*)(Ah + m * BKP + k4 * 4) = h4;
            *(ushort4*)(Al + m * BKP + k4 * 4) = l4;
        }
        __syncthreads();

        #pragma unroll
        for (int k16 = 0; k16 < BK / 16; k16++) {
            int kc = k16 * 16;
            int kg = c * BK + kc;
            uint32_t ah[2][4], al[2][4];
            #pragma unroll
            for (int mi = 0; mi < 2; mi++) {
                int ar = wm * 32 + mi * 16 + a_row;
                LDM_X4(ah[mi], smem_u32(Ah + ar * BKP + kc + a_col));
                LDM_X4(al[mi], smem_u32(Al + ar * BKP + kc + a_col));
            }
            #pragma unroll
            for (int ng = 0; ng < NFR / 2; ng++) {
                int n0 = wn * TN_W + ng * 16;
                uint32_t bh[4], bl[4];
                LDM_X4(bh, smem_u32(Wh + (n0 + b_row) * KP + kg + b_col));
                LDM_X4(bl, smem_u32(Wl + (n0 + b_row) * KP + kg + b_col));
                #pragma unroll
                for (int mi = 0; mi < 2; mi++) {
                    MMA_BF16(acc[mi][2 * ng],     ah[mi], (bh + 0));
                    MMA_BF16(acc[mi][2 * ng + 1], ah[mi], (bh + 2));
                    MMA_BF16(acc[mi][2 * ng],     ah[mi], (bl + 0));
                    MMA_BF16(acc[mi][2 * ng + 1], ah[mi], (bl + 2));
                    MMA_BF16(acc[mi][2 * ng],     al[mi], (bh + 0));
                    MMA_BF16(acc[mi][2 * ng + 1], al[mi], (bh + 2));
                }
            }
        }
    }

    #pragma unroll
    for (int mi = 0; mi < 2; mi++) {
        int r = row0 + wm * 32 + mi * 16 + (lane >> 2);
        #pragma unroll
        for (int nf = 0; nf < NFR; nf++) {
            int col = wn * TN_W + nf * 8 + (lane & 3) * 2;
            if (r < M)
                *(__half2*)(C + (size_t)r * N + col) =
                    __floats2half2_rn(acc[mi][nf][0], acc[mi][nf][1]);
            if (r + 8 < M)
                *(__half2*)(C + (size_t)(r + 8) * N + col) =
                    __floats2half2_rn(acc[mi][nf][2], acc[mi][nf][3]);
        }
    }
}

// ---------------- gather1: agg1 = (sum ns[s]*m1[s]) * nd + b1 (fp32) -------
__global__ __launch_bounds__(256) void gather1_kernel(
    const __half* __restrict__ m, float* __restrict__ agg,
    const float* __restrict__ bias, int N)
{
    constexpr int C = HIDDEN;
    int n    = (blockIdx.x * blockDim.x + threadIdx.x) >> 5;
    int lane = threadIdx.x & 31;
    if (n >= N) return;
    int beg = g_row_ptr[n];
    int cnt = g_degi_in[n];
    const int* __restrict__ ss = g_sorted_src + beg;

    float4 acc = make_float4(0.f, 0.f, 0.f, 0.f);
    int e = 0;
    for (; e + 4 <= cnt; e += 4) {
        int s0 = ss[e], s1 = ss[e + 1], s2 = ss[e + 2], s3 = ss[e + 3];
        float n0 = __ldg(&g_ns[s0]), n1 = __ldg(&g_ns[s1]);
        float n2 = __ldg(&g_ns[s2]), n3 = __ldg(&g_ns[s3]);
        uint2 r0 = __ldg((const uint2*)(m + (size_t)s0 * C) + lane);
        uint2 r1 = __ldg((const uint2*)(m + (size_t)s1 * C) + lane);
        uint2 r2 = __ldg((const uint2*)(m + (size_t)s2 * C) + lane);
        uint2 r3 = __ldg((const uint2*)(m + (size_t)s3 * C) + lane);
        float2 a, b;
        a = __half22float2(*(__half2*)&r0.x); b = __half22float2(*(__half2*)&r0.y);
        acc.x = fmaf(a.x, n0, acc.x); acc.y = fmaf(a.y, n0, acc.y);
        acc.z = fmaf(b.x, n0, acc.z); acc.w = fmaf(b.y, n0, acc.w);
        a = __half22float2(*(__half2*)&r1.x); b = __half22float2(*(__half2*)&r1.y);
        acc.x = fmaf(a.x, n1, acc.x); acc.y = fmaf(a.y, n1, acc.y);
        acc.z = fmaf(b.x, n1, acc.z); acc.w = fmaf(b.y, n1, acc.w);
        a = __half22float2(*(__half2*)&r2.x); b = __half22float2(*(__half2*)&r2.y);
        acc.x = fmaf(a.x, n2, acc.x); acc.y = fmaf(a.y, n2, acc.y);
        acc.z = fmaf(b.x, n2, acc.z); acc.w = fmaf(b.y, n2, acc.w);
        a = __half22float2(*(__half2*)&r3.x); b = __half22float2(*(__half2*)&r3.y);
        acc.x = fmaf(a.x, n3, acc.x); acc.y = fmaf(a.y, n3, acc.y);
        acc.z = fmaf(b.x, n3, acc.z); acc.w = fmaf(b.y, n3, acc.w);
    }
    for (; e < cnt; e++) {
        int s0 = ss[e];
        float n0 = __ldg(&g_ns[s0]);
        uint2 r0 = __ldg((const uint2*)(m + (size_t)s0 * C) + lane);
        float2 a = __half22float2(*(__half2*)&r0.x);
        float2 b = __half22float2(*(__half2*)&r0.y);
        acc.x = fmaf(a.x, n0, acc.x); acc.y = fmaf(a.y, n0, acc.y);
        acc.z = fmaf(b.x, n0, acc.z); acc.w = fmaf(b.y, n0, acc.w);
    }
    float nd = g_nd[n];
    float4 bb = ((const float4*)bias)[lane];
    acc.x = acc.x * nd + bb.x; acc.y = acc.y * nd + bb.y;
    acc.z = acc.z * nd + bb.z; acc.w = acc.w * nd + bb.w;
    ((float4*)(agg + (size_t)n * C))[lane] = acc;
}

// ---------------- GEMM2: m2(fp16) = (relu(agg1)*ns) @ W2 -------------------
__global__ __launch_bounds__(256) void gemm2_kernel(
    const float* __restrict__ A,
    const __nv_bfloat16* __restrict__ Whi, const __nv_bfloat16* __restrict__ Wlo,
    __half* __restrict__ C, const float* __restrict__ ns, int M)
{
    constexpr int N = OUT_FEATS, KTOT = HIDDEN;
    constexpr int BK = 64, BKP = BK + 8, KP = KTOT + 8;
    constexpr int TN_W = N / 2;          // 32
    constexpr int NFR = TN_W / 8;        // 4
    constexpr int WB = N * KP;

    extern __shared__ __nv_bfloat16 smbuf[];
    __nv_bfloat16* Wh = smbuf;
    __nv_bfloat16* Wl = smbuf + WB;
    __nv_bfloat16* Ah = smbuf + 2 * (size_t)WB;
    __nv_bfloat16* Al = Ah + 128 * BKP;

    const int tid = threadIdx.x, lane = tid & 31, wid = tid >> 5;
    const int wm = wid & 3, wn = wid >> 2;
    const int row0 = blockIdx.x * 128;

    {
        const float4* s1 = (const float4*)Whi;
        const float4* s2 = (const float4*)Wlo;
        float4* d1 = (float4*)Wh;
        float4* d2 = (float4*)Wl;
        #pragma unroll 4
        for (int i = tid; i < WB / 8; i += 256) { d1[i] = s1[i]; d2[i] = s2[i]; }
    }

    float acc[2][NFR][4] = {};

    const int a_row = (lane & 7) + ((lane >> 3) & 1) * 8;
    const int a_col = (lane >> 4) * 8;
    const int b_row = (lane & 7) + (lane >> 4) * 8;
    const int b_col = ((lane >> 3) & 1) * 8;

    for (int c = 0; c < KTOT / BK; c++) {
        __syncthreads();
        #pragma unroll
        for (int l = 0; l < 8; l++) {
            int idx = tid + l * 256;
            int m = idx >> 4, k4 = idx & 15;
            int gm = row0 + m;
            float4 v = make_float4(0.f, 0.f, 0.f, 0.f);
            if (gm < M) {
                v = *(const float4*)(A + (size_t)gm * KTOT + c * BK + k4 * 4);
                float s = ns[gm];
                v.x = fmaxf(v.x, 0.f) * s; v.y = fmaxf(v.y, 0.f) * s;
                v.z = fmaxf(v.z, 0.f) * s; v.w = fmaxf(v.w, 0.f) * s;
            }
            ushort4 h4, l4;
            split_bf16(v.x, h4.x, l4.x);
            split_bf16(v.y, h4.y, l4.y);
            split_bf16(v.z, h4.z, l4.z);
            split_bf16(v.w, h4.w, l4.w);
            *(ushort4*)(Ah + m * BKP + k4 * 4) = h4;
            *(ushort4*)(Al + m * BKP + k4 * 4) = l4;
        }
        __syncthreads();

        #pragma unroll
        for (int k16 = 0; k16 < BK / 16; k16++) {
            int kc = k16 * 16;
            int kg = c * BK + kc;
            uint32_t ah[2][4], al[2][4];
            #pragma unroll
            for (int mi = 0; mi < 2; mi++) {
                int ar = wm * 32 + mi * 16 + a_row;
                LDM_X4(ah[mi], smem_u32(Ah + ar * BKP + kc + a_col));
                LDM_X4(al[mi], smem_u32(Al + ar * BKP + kc + a_col));
            }
            #pragma unroll
            for (int ng = 0; ng < NFR / 2; ng++) {
                int n0 = wn * TN_W + ng * 16;
                uint32_t bh[4], bl[4];
                LDM_X4(bh, smem_u32(Wh + (n0 + b_row) * KP + kg + b_col));
                LDM_X4(bl, smem_u32(Wl + (n0 + b_row) * KP + kg + b_col));
                #pragma unroll
                for (int mi = 0; mi < 2; mi++) {
                    MMA_BF16(acc[mi][2 * ng],     ah[mi], (bh + 0));
                    MMA_BF16(acc[mi][2 * ng + 1], ah[mi], (bh + 2));
                    MMA_BF16(acc[mi][2 * ng],     ah[mi], (bl + 0));
                    MMA_BF16(acc[mi][2 * ng + 1], ah[mi], (bl + 2));
                    MMA_BF16(acc[mi][2 * ng],     al[mi], (bh + 0));
                    MMA_BF16(acc[mi][2 * ng + 1], al[mi], (bh + 2));
                }
            }
        }
    }

    #pragma unroll
    for (int mi = 0; mi < 2; mi++) {
        int r = row0 + wm * 32 + mi * 16 + (lane >> 2);
        #pragma unroll
        for (int nf = 0; nf < NFR; nf++) {
            int col = wn * TN_W + nf * 8 + (lane & 3) * 2;
            if (r < M)
                *(__half2*)(C + (size_t)r * N + col) =
                    __floats2half2_rn(acc[mi][nf][0], acc[mi][nf][1]);
            if (r + 8 < M)
                *(__half2*)(C + (size_t)(r + 8) * N + col) =
                    __floats2half2_rn(acc[mi][nf][2], acc[mi][nf][3]);
        }
    }
}

// ---------------- gather2: out = (sum m2[src]) * nd + b2 (fp32) ------------
__global__ __launch_bounds__(256) void gather2_kernel(
    const __half* __restrict__ m, float* __restrict__ agg,
    const float* __restrict__ bias, int N)
{
    constexpr int C = OUT_FEATS;
    int n    = (blockIdx.x * blockDim.x + threadIdx.x) >> 5;
    int lane = threadIdx.x & 31;
    if (n >= N) return;
    int beg = g_row_ptr[n];
    int cnt = g_degi_in[n];
    const int* __restrict__ ss = g_sorted_src + beg;

    float2 acc = make_float2(0.f, 0.f);
    int e = 0;
    for (; e + 4 <= cnt; e += 4) {
        int s0 = ss[e], s1 = ss[e + 1], s2 = ss[e + 2], s3 = ss[e + 3];
        uint32_t r0 = __ldg((const uint32_t*)(m + (size_t)s0 * C) + lane);
        uint32_t r1 = __ldg((const uint32_t*)(m + (size_t)s1 * C) + lane);
        uint32_t r2 = __ldg((const uint32_t*)(m + (size_t)s2 * C) + lane);
        uint32_t r3 = __ldg((const uint32_t*)(m + (size_t)s3 * C) + lane);
        float2 a;
        a = __half22float2(*(__half2*)&r0); acc.x += a.x; acc.y += a.y;
        a = __half22float2(*(__half2*)&r1); acc.x += a.x; acc.y += a.y;
        a = __half22float2(*(__half2*)&r2); acc.x += a.x; acc.y += a.y;
        a = __half22float2(*(__half2*)&r3); acc.x += a.x; acc.y += a.y;
    }
    for (; e < cnt; e++) {
        uint32_t r0 = __ldg((const uint32_t*)(m + (size_t)ss[e] * C) + lane);
        float2 a = __half22float2(*(__half2*)&r0);
        acc.x += a.x; acc.y += a.y;
    }
    float nd = g_nd[n];
    float2 bb = ((const float2*)bias)[lane];
    acc.x = acc.x * nd + bb.x; acc.y = acc.y * nd + bb.y;
    ((float2*)(agg + (size_t)n * C))[lane] = acc;
}

// ---------------- launch ---------------------------------------------------
extern "C" void kernel_launch(void* const* d_in, const int* in_sizes, int n_in,
                              void* d_out, int out_size) {
    const float* x  = (const float*)d_in[0];
    const void*  src = d_in[1];
    const void*  dst = d_in[2];
    const float* W1 = (const float*)d_in[3];
    const float* b1 = (const float*)d_in[4];
    const float* W2 = (const float*)d_in[5];
    const float* b2 = (const float*)d_in[6];
    float* out = (float*)d_out;

    int N = in_sizes[0] / IN_FEATS;   // 50000
    int E = in_sizes[1];              // 800000
    int nb = (N + SCAN_BLK - 1) / SCAN_BLK;
    int G1 = (N + 127) / 128;

    void *p_dego, *p_degi, *p_agg1, *p_m1, *p_m2, *p_ns;
    void *p_w1hi, *p_w1lo, *p_w2hi, *p_w2lo;
    cudaGetSymbolAddress(&p_dego, g_degi_out);
    cudaGetSymbolAddress(&p_degi, g_degi_in);
    cudaGetSymbolAddress(&p_agg1, g_agg1);
    cudaGetSymbolAddress(&p_m1,   g_m1);
    cudaGetSymbolAddress(&p_m2,   g_m2);
    cudaGetSymbolAddress(&p_ns,   g_ns);
    cudaGetSymbolAddress(&p_w1hi, g_w1hi);
    cudaGetSymbolAddress(&p_w1lo, g_w1lo);
    cudaGetSymbolAddress(&p_w2hi, g_w2hi);
    cudaGetSymbolAddress(&p_w2lo, g_w2lo);

    constexpr int SMEM1 = 2 * HIDDEN * (IN_FEATS + 8) * 2 + 2 * 128 * 72 * 2;     // 172032
    constexpr int SMEM2 = 2 * OUT_FEATS * (HIDDEN + 8) * 2 + 2 * 128 * 72 * 2;    // 71680
    cudaFuncSetAttribute(gemm1_deg_kernel,
                         cudaFuncAttributeMaxDynamicSharedMemorySize, SMEM1);
    cudaFuncSetAttribute(gemm2_kernel,
                         cudaFuncAttributeMaxDynamicSharedMemorySize, SMEM2);

    cudaMemsetAsync(p_dego, 0, (size_t)N * sizeof(int));
    cudaMemsetAsync(p_degi, 0, (size_t)N * sizeof(int));

    detect_i64_kernel<<<1, 1>>>((const unsigned int*)src, E);

    wprep_kernel<IN_FEATS, HIDDEN><<<(IN_FEATS * HIDDEN + 255) / 256, 256>>>(
        W1, (__nv_bfloat16*)p_w1hi, (__nv_bfloat16*)p_w1lo);
    wprep_kernel<HIDDEN, OUT_FEATS><<<(HIDDEN * OUT_FEATS + 255) / 256, 256>>>(
        W2, (__nv_bfloat16*)p_w2hi, (__nv_bfloat16*)p_w2lo);

    // MEGA: gemm1 (m1 = x @ W1, no ns) + degree counting overlapped
    gemm1_deg_kernel<<<G1 + DEG_BLOCKS, 256, SMEM1>>>(
        x, (const __nv_bfloat16*)p_w1hi, (const __nv_bfloat16*)p_w1lo,
        (__half*)p_m1, N, G1, src, dst, E);

    scan_block_sums<<<nb, SCAN_BLK>>>(N);
    scan_partials<<<1, SCAN_BLK>>>(nb);
    scan_final<<<nb, SCAN_BLK>>>(N);          // row_ptr + norms + cursor=0
    fill_csr_kernel<<<(E / 4 + 255) / 256, 256>>>(src, dst, E);

    // agg1 = (sum ns[s]*m1[s]) * nd + b1
    gather1_kernel<<<(N * 32 + 255) / 256, 256>>>(
        (const __half*)p_m1, (float*)p_agg1, b1, N);

    // m2 = (relu(agg1) * ns) @ W2  -> fp16
    gemm2_kernel<<<G1, 256, SMEM2>>>(
        (const float*)p_agg1, (const __nv_bfloat16*)p_w2hi, (const __nv_bfloat16*)p_w2lo,
        (__half*)p_m2, (const float*)p_ns, N);

    // out = (sum m2[src]) * nd + b2
    gather2_kernel<<<(N * 32 + 255) / 256, 256>>>(
        (const __half*)p_m2, out, b2, N);
}

// round 13
// speedup vs baseline: 1.2310x; 1.0259x over previous
#include <cuda_runtime.h>
#include <cuda_bf16.h>
#include <cuda_fp16.h>
#include <math.h>
#include <cstdint>

#define IN_FEATS 256
#define HIDDEN   128
#define OUT_FEATS 64
#define MAX_NODES 50048
#define MAX_EDGES 800000
#define SCAN_BLK  256
#define DEG_BLOCKS 112

// ---------------- scratch (static device globals) --------------------------
__device__ int   g_degi_out[MAX_NODES];
__device__ int   g_degi_in[MAX_NODES];
__device__ float g_ns[MAX_NODES];
__device__ float g_nd[MAX_NODES];
__device__ int   g_row_ptr[MAX_NODES];
__device__ int   g_cursor[MAX_NODES];
__device__ int   g_sorted_src[MAX_EDGES];
__device__ int   g_bsum[(MAX_NODES + SCAN_BLK - 1) / SCAN_BLK];
__device__ int   g_bpre[(MAX_NODES + SCAN_BLK - 1) / SCAN_BLK];
__device__ __align__(16) __half g_m1[(size_t)MAX_NODES * HIDDEN];
__device__ float g_agg1[(size_t)MAX_NODES * HIDDEN];
__device__ __align__(16) __half g_m2[(size_t)MAX_NODES * OUT_FEATS];
// W images, CHUNKED layout: [chunk][N][72] bf16 (chunk = 64 K-cols + 8 pad)
__device__ __align__(16) __nv_bfloat16 g_w1hi[(IN_FEATS / 64) * HIDDEN * 72];
__device__ __align__(16) __nv_bfloat16 g_w1lo[(IN_FEATS / 64) * HIDDEN * 72];
__device__ __align__(16) __nv_bfloat16 g_w2hi[(HIDDEN / 64) * OUT_FEATS * 72];
__device__ __align__(16) __nv_bfloat16 g_w2lo[(HIDDEN / 64) * OUT_FEATS * 72];
__device__ int   g_is64;

// ---------------- PTX helpers ----------------------------------------------
__device__ __forceinline__ uint32_t smem_u32(const void* p) {
    uint32_t a;
    asm("{ .reg .u64 t; cvta.to.shared.u64 t, %1; cvt.u32.u64 %0, t; }" : "=r"(a) : "l"(p));
    return a;
}

#define LDM_X4(r, a) \
    asm volatile("ldmatrix.sync.aligned.m8n8.x4.shared.b16 {%0,%1,%2,%3}, [%4];" \
        : "=r"((r)[0]), "=r"((r)[1]), "=r"((r)[2]), "=r"((r)[3]) : "r"(a))

#define MMA_BF16(d, a, b) \
    asm volatile("mma.sync.aligned.m16n8k16.row.col.f32.bf16.bf16.f32 " \
        "{%0,%1,%2,%3}, {%4,%5,%6,%7}, {%8,%9}, {%0,%1,%2,%3};" \
        : "+f"((d)[0]), "+f"((d)[1]), "+f"((d)[2]), "+f"((d)[3]) \
        : "r"((a)[0]), "r"((a)[1]), "r"((a)[2]), "r"((a)[3]), \
          "r"((b)[0]), "r"((b)[1]))

__device__ __forceinline__ void split_bf16(float v, unsigned short& h, unsigned short& l) {
    __nv_bfloat16 hb = __float2bfloat16(v);
    __nv_bfloat16 lb = __float2bfloat16(v - __bfloat162float(hb));
    h = *(unsigned short*)&hb;
    l = *(unsigned short*)&lb;
}

// ---------------- index dtype detector ------------------------------------
__global__ void detect_i64_kernel(const unsigned int* __restrict__ words, int E) {
    int is64 = 1;
    int nchk = E < 32 ? E : 32;
    for (int i = 0; i < nchk; i++) {
        if (words[2 * i + 1] != 0u) { is64 = 0; break; }
    }
    g_is64 = is64;
}

__device__ __forceinline__ int load_idx(const void* p, int i) {
    if (g_is64) return (int)((const long long*)p)[i];
    return ((const int*)p)[i];
}

// ---------------- exclusive scan of g_degi_in -> g_row_ptr -----------------
__global__ void scan_block_sums(int N) {
    __shared__ int sm[SCAN_BLK];
    int i = blockIdx.x * SCAN_BLK + threadIdx.x;
    int v = (i < N) ? g_degi_in[i] : 0;
    sm[threadIdx.x] = v;
    __syncthreads();
    for (int s = SCAN_BLK / 2; s > 0; s >>= 1) {
        if (threadIdx.x < s) sm[threadIdx.x] += sm[threadIdx.x + s];
        __syncthreads();
    }
    if (threadIdx.x == 0) g_bsum[blockIdx.x] = sm[0];
}

__global__ void scan_partials(int nb) {
    __shared__ int sm[SCAN_BLK];
    int v = (threadIdx.x < nb) ? g_bsum[threadIdx.x] : 0;
    sm[threadIdx.x] = v;
    __syncthreads();
    for (int off = 1; off < SCAN_BLK; off <<= 1) {
        int t = (threadIdx.x >= off) ? sm[threadIdx.x - off] : 0;
        __syncthreads();
        sm[threadIdx.x] += t;
        __syncthreads();
    }
    if (threadIdx.x < nb) g_bpre[threadIdx.x] = sm[threadIdx.x] - v;
}

// scan_final also computes norms and zeroes the cursor (fused)
__global__ void scan_final(int N) {
    __shared__ int sm[SCAN_BLK];
    int i = blockIdx.x * SCAN_BLK + threadIdx.x;
    int v = (i < N) ? g_degi_in[i] : 0;
    sm[threadIdx.x] = v;
    __syncthreads();
    for (int off = 1; off < SCAN_BLK; off <<= 1) {
        int t = (threadIdx.x >= off) ? sm[threadIdx.x - off] : 0;
        __syncthreads();
        sm[threadIdx.x] += t;
        __syncthreads();
    }
    if (i < N) {
        g_row_ptr[i] = g_bpre[blockIdx.x] + sm[threadIdx.x] - v;
        g_cursor[i] = 0;
        g_ns[i] = rsqrtf(fmaxf((float)g_degi_out[i], 1.0f));
        g_nd[i] = rsqrtf(fmaxf((float)v, 1.0f));
    }
}

// ---------------- counting-sort fill (4 edges/thread) ----------------------
__global__ void fill_csr_kernel(const void* __restrict__ src, const void* __restrict__ dst, int E) {
    int e0 = (blockIdx.x * blockDim.x + threadIdx.x) * 4;
    int s[4], d[4];
    #pragma unroll
    for (int i = 0; i < 4; i++) {
        int e = e0 + i;
        if (e < E) { s[i] = load_idx(src, e); d[i] = load_idx(dst, e); }
        else { s[i] = -1; d[i] = -1; }
    }
    #pragma unroll
    for (int i = 0; i < 4; i++) {
        if (s[i] >= 0) {
            int pos = g_row_ptr[d[i]] + atomicAdd(&g_cursor[d[i]], 1);
            g_sorted_src[pos] = s[i];
        }
    }
}

// ---------------- W prep: fp32 W[K,N] -> chunked bf16 hi/lo [chunk][N][72] -
template <int K, int N>
__global__ void wprep_kernel(const float* __restrict__ W,
                             __nv_bfloat16* __restrict__ hi,
                             __nv_bfloat16* __restrict__ lo) {
    int idx = blockIdx.x * blockDim.x + threadIdx.x;
    if (idx >= K * N) return;
    int n = idx / K;
    int k = idx - n * K;
    float v = W[(size_t)k * N + n];
    unsigned short h, l;
    split_bf16(v, h, l);
    int c = k >> 6, kc = k & 63;
    size_t off = ((size_t)c * N + n) * 72 + kc;
    hi[off] = *(__nv_bfloat16*)&h;
    lo[off] = *(__nv_bfloat16*)&l;
}

// ---------------- MEGA: gemm1 (m1 = x @ W1, unscaled) + degree counting ----
__global__ __launch_bounds__(256) void gemm1_deg_kernel(
    const float* __restrict__ A,
    const __nv_bfloat16* __restrict__ Whi, const __nv_bfloat16* __restrict__ Wlo,
    __half* __restrict__ C, int M, int G1,
    const void* __restrict__ src, const void* __restrict__ dst, int E)
{
    constexpr int N = HIDDEN, KTOT = IN_FEATS;
    constexpr int BK = 64, BKP = 72;
    constexpr int TN_W = N / 2;          // 64
    constexpr int NFR = TN_W / 8;        // 8
    constexpr int WCH = N * BKP;         // W chunk elems: 9216

    const int tid = threadIdx.x;

    // ---- degree-counting role ----
    if (blockIdx.x >= G1) {
        int b = blockIdx.x - G1;
        for (int e = b * 256 + tid; e < E; e += DEG_BLOCKS * 256) {
            int s = load_idx(src, e);
            int d = load_idx(dst, e);
            atomicAdd(&g_degi_out[s], 1);
            atomicAdd(&g_degi_in[d], 1);
        }
        return;
    }

    // ---- GEMM role ----
    extern __shared__ __nv_bfloat16 smbuf[];
    __nv_bfloat16* Wh = smbuf;                 // [N][72]
    __nv_bfloat16* Wl = smbuf + WCH;
    __nv_bfloat16* Ah = smbuf + 2 * (size_t)WCH;   // [128][72]
    __nv_bfloat16* Al = Ah + 128 * BKP;

    const int lane = tid & 31, wid = tid >> 5;
    const int wm = wid & 3, wn = wid >> 2;
    const int row0 = blockIdx.x * 128;

    float acc[2][NFR][4] = {};

    const int a_row = (lane & 7) + ((lane >> 3) & 1) * 8;
    const int a_col = (lane >> 4) * 8;
    const int b_row = (lane & 7) + (lane >> 4) * 8;
    const int b_col = ((lane >> 3) & 1) * 8;

    for (int c = 0; c < KTOT / BK; c++) {
        __syncthreads();
        // stream this chunk's W slice into smem (contiguous in chunked layout)
        {
            const float4* s1 = (const float4*)(Whi + (size_t)c * WCH);
            const float4* s2 = (const float4*)(Wlo + (size_t)c * WCH);
            float4* d1 = (float4*)Wh;
            float4* d2 = (float4*)Wl;
            #pragma unroll
            for (int i = tid; i < WCH / 8; i += 256) { d1[i] = s1[i]; d2[i] = s2[i]; }
        }
        // load + convert A chunk: 128 rows x 64 cols fp32 -> bf16 hi/lo
        #pragma unroll
        for (int l = 0; l < 8; l++) {
            int idx = tid + l * 256;
            int m = idx >> 4, k4 = idx & 15;
            int gm = row0 + m;
            float4 v = make_float4(0.f, 0.f, 0.f, 0.f);
            if (gm < M)
                v = *(const float4*)(A + (size_t)gm * KTOT + c * BK + k4 * 4);
            ushort4 h4, l4;
            split_bf16(v.x, h4.x, l4.x);
            split_bf16(v.y, h4.y, l4.y);
            split_bf16(v.z, h4.z, l4.z);
            split_bf16(v.w, h4.w, l4.w);
            *(ushort4*)(Ah + m * BKP + k4 * 4) = h4;
            *(ushort4*)(Al + m * BKP + k4 * 4) = l4;
        }
        __syncthreads();

        #pragma unroll
        for (int k16 = 0; k16 < BK / 16; k16++) {
            int kc = k16 * 16;
            uint32_t ah[2][4], al[2][4];
            #pragma unroll
            for (int mi = 0; mi < 2; mi++) {
                int ar = wm * 32 + mi * 16 + a_row;
                LDM_X4(ah[mi], smem_u32(Ah + ar * BKP + kc + a_col));
                LDM_X4(al[mi], smem_u32(Al + ar * BKP + kc + a_col));
            }
            #pragma unroll
            for (int ng = 0; ng < NFR / 2; ng++) {
                int n0 = wn * TN_W + ng * 16;
                uint32_t bh[4], bl[4];
                LDM_X4(bh, smem_u32(Wh + (n0 + b_row) * BKP + kc + b_col));
                LDM_X4(bl, smem_u32(Wl + (n0 + b_row) * BKP + kc + b_col));
                #pragma unroll
                for (int mi = 0; mi < 2; mi++) {
                    MMA_BF16(acc[mi][2 * ng],     ah[mi], (bh + 0));
                    MMA_BF16(acc[mi][2 * ng + 1], ah[mi], (bh + 2));
                    MMA_BF16(acc[mi][2 * ng],     ah[mi], (bl + 0));
                    MMA_BF16(acc[mi][2 * ng + 1], ah[mi], (bl + 2));
                    MMA_BF16(acc[mi][2 * ng],     al[mi], (bh + 0));
                    MMA_BF16(acc[mi][2 * ng + 1], al[mi], (bh + 2));
                }
            }
        }
    }

    #pragma unroll
    for (int mi = 0; mi < 2; mi++) {
        int r = row0 + wm * 32 + mi * 16 + (lane >> 2);
        #pragma unroll
        for (int nf = 0; nf < NFR; nf++) {
            int col = wn * TN_W + nf * 8 + (lane & 3) * 2;
            if (r < M)
                *(__half2*)(C + (size_t)r * N + col) =
                    __floats2half2_rn(acc[mi][nf][0], acc[mi][nf][1]);
            if (r + 8 < M)
                *(__half2*)(C + (size_t)(r + 8) * N + col) =
                    __floats2half2_rn(acc[mi][nf][2], acc[mi][nf][3]);
        }
    }
}

// ---------------- gather1: agg1 = (sum ns[s]*m1[s]) * nd + b1 (fp32) -------
__global__ __launch_bounds__(256) void gather1_kernel(
    const __half* __restrict__ m, float* __restrict__ agg,
    const float* __restrict__ bias, int N)
{
    constexpr int C = HIDDEN;
    int n    = (blockIdx.x * blockDim.x + threadIdx.x) >> 5;
    int lane = threadIdx.x & 31;
    if (n >= N) return;
    int beg = g_row_ptr[n];
    int cnt = g_degi_in[n];
    const int* __restrict__ ss = g_sorted_src + beg;

    float4 acc = make_float4(0.f, 0.f, 0.f, 0.f);
    int e = 0;
    for (; e + 4 <= cnt; e += 4) {
        int s0 = ss[e], s1 = ss[e + 1], s2 = ss[e + 2], s3 = ss[e + 3];
        float n0 = __ldg(&g_ns[s0]), n1 = __ldg(&g_ns[s1]);
        float n2 = __ldg(&g_ns[s2]), n3 = __ldg(&g_ns[s3]);
        uint2 r0 = __ldg((const uint2*)(m + (size_t)s0 * C) + lane);
        uint2 r1 = __ldg((const uint2*)(m + (size_t)s1 * C) + lane);
        uint2 r2 = __ldg((const uint2*)(m + (size_t)s2 * C) + lane);
        uint2 r3 = __ldg((const uint2*)(m + (size_t)s3 * C) + lane);
        float2 a, b;
        a = __half22float2(*(__half2*)&r0.x); b = __half22float2(*(__half2*)&r0.y);
        acc.x = fmaf(a.x, n0, acc.x); acc.y = fmaf(a.y, n0, acc.y);
        acc.z = fmaf(b.x, n0, acc.z); acc.w = fmaf(b.y, n0, acc.w);
        a = __half22float2(*(__half2*)&r1.x); b = __half22float2(*(__half2*)&r1.y);
        acc.x = fmaf(a.x, n1, acc.x); acc.y = fmaf(a.y, n1, acc.y);
        acc.z = fmaf(b.x, n1, acc.z); acc.w = fmaf(b.y, n1, acc.w);
        a = __half22float2(*(__half2*)&r2.x); b = __half22float2(*(__half2*)&r2.y);
        acc.x = fmaf(a.x, n2, acc.x); acc.y = fmaf(a.y, n2, acc.y);
        acc.z = fmaf(b.x, n2, acc.z); acc.w = fmaf(b.y, n2, acc.w);
        a = __half22float2(*(__half2*)&r3.x); b = __half22float2(*(__half2*)&r3.y);
        acc.x = fmaf(a.x, n3, acc.x); acc.y = fmaf(a.y, n3, acc.y);
        acc.z = fmaf(b.x, n3, acc.z); acc.w = fmaf(b.y, n3, acc.w);
    }
    for (; e < cnt; e++) {
        int s0 = ss[e];
        float n0 = __ldg(&g_ns[s0]);
        uint2 r0 = __ldg((const uint2*)(m + (size_t)s0 * C) + lane);
        float2 a = __half22float2(*(__half2*)&r0.x);
        float2 b = __half22float2(*(__half2*)&r0.y);
        acc.x = fmaf(a.x, n0, acc.x); acc.y = fmaf(a.y, n0, acc.y);
        acc.z = fmaf(b.x, n0, acc.z); acc.w = fmaf(b.y, n0, acc.w);
    }
    float nd = g_nd[n];
    float4 bb = ((const float4*)bias)[lane];
    acc.x = acc.x * nd + bb.x; acc.y = acc.y * nd + bb.y;
    acc.z = acc.z * nd + bb.z; acc.w = acc.w * nd + bb.w;
    ((float4*)(agg + (size_t)n * C))[lane] = acc;
}

// ---------------- GEMM2: m2(fp16) = (relu(agg1)*ns) @ W2 -------------------
__global__ __launch_bounds__(256) void gemm2_kernel(
    const float* __restrict__ A,
    const __nv_bfloat16* __restrict__ Whi, const __nv_bfloat16* __restrict__ Wlo,
    __half* __restrict__ C, const float* __restrict__ ns, int M)
{
    constexpr int N = OUT_FEATS, KTOT = HIDDEN;
    constexpr int BK = 64, BKP = 72;
    constexpr int TN_W = N / 2;          // 32
    constexpr int NFR = TN_W / 8;        // 4
    constexpr int WCH = N * BKP;         // 4608

    extern __shared__ __nv_bfloat16 smbuf[];
    __nv_bfloat16* Wh = smbuf;
    __nv_bfloat16* Wl = smbuf + WCH;
    __nv_bfloat16* Ah = smbuf + 2 * (size_t)WCH;
    __nv_bfloat16* Al = Ah + 128 * BKP;

    const int tid = threadIdx.x, lane = tid & 31, wid = tid >> 5;
    const int wm = wid & 3, wn = wid >> 2;
    const int row0 = blockIdx.x * 128;

    float acc[2][NFR][4] = {};

    const int a_row = (lane & 7) + ((lane >> 3) & 1) * 8;
    const int a_col = (lane >> 4) * 8;
    const int b_row = (lane & 7) + (lane >> 4) * 8;
    const int b_col = ((lane >> 3) & 1) * 8;

    for (int c = 0; c < KTOT / BK; c++) {
        __syncthreads();
        {
            const float4* s1 = (const float4*)(Whi + (size_t)c * WCH);
            const float4* s2 = (const float4*)(Wlo + (size_t)c * WCH);
            float4* d1 = (float4*)Wh;
            float4* d2 = (float4*)Wl;
            #pragma unroll
            for (int i = tid; i < WCH / 8; i += 256) { d1[i] = s1[i]; d2[i] = s2[i]; }
        }
        #pragma unroll
        for (int l = 0; l < 8; l++) {
            int idx = tid + l * 256;
            int m = idx >> 4, k4 = idx & 15;
            int gm = row0 + m;
            float4 v = make_float4(0.f, 0.f, 0.f, 0.f);
            if (gm < M) {
                v = *(const float4*)(A + (size_t)gm * KTOT + c * BK + k4 * 4);
                float s = ns[gm];
                v.x = fmaxf(v.x, 0.f) * s; v.y = fmaxf(v.y, 0.f) * s;
                v.z = fmaxf(v.z, 0.f) * s; v.w = fmaxf(v.w, 0.f) * s;
            }
            ushort4 h4, l4;
            split_bf16(v.x, h4.x, l4.x);
            split_bf16(v.y, h4.y, l4.y);
            split_bf16(v.z, h4.z, l4.z);
            split_bf16(v.w, h4.w, l4.w);
            *(ushort4*)(Ah + m * BKP + k4 * 4) = h4;
            *(ushort4*)(Al + m * BKP + k4 * 4) = l4;
        }
        __syncthreads();

        #pragma unroll
        for (int k16 = 0; k16 < BK / 16; k16++) {
            int kc = k16 * 16;
            uint32_t ah[2][4], al[2][4];
            #pragma unroll
            for (int mi = 0; mi < 2; mi++) {
                int ar = wm * 32 + mi * 16 + a_row;
                LDM_X4(ah[mi], smem_u32(Ah + ar * BKP + kc + a_col));
                LDM_X4(al[mi], smem_u32(Al + ar * BKP + kc + a_col));
            }
            #pragma unroll
            for (int ng = 0; ng < NFR / 2; ng++) {
                int n0 = wn * TN_W + ng * 16;
                uint32_t bh[4], bl[4];
                LDM_X4(bh, smem_u32(Wh + (n0 + b_row) * BKP + kc + b_col));
                LDM_X4(bl, smem_u32(Wl + (n0 + b_row) * BKP + kc + b_col));
                #pragma unroll
                for (int mi = 0; mi < 2; mi++) {
                    MMA_BF16(acc[mi][2 * ng],     ah[mi], (bh + 0));
                    MMA_BF16(acc[mi][2 * ng + 1], ah[mi], (bh + 2));
                    MMA_BF16(acc[mi][2 * ng],     ah[mi], (bl + 0));
                    MMA_BF16(acc[mi][2 * ng + 1], ah[mi], (bl + 2));
                    MMA_BF16(acc[mi][2 * ng],     al[mi], (bh + 0));
                    MMA_BF16(acc[mi][2 * ng + 1], al[mi], (bh + 2));
                }
            }
        }
    }

    #pragma unroll
    for (int mi = 0; mi < 2; mi++) {
        int r = row0 + wm * 32 + mi * 16 + (lane >> 2);
        #pragma unroll
        for (int nf = 0; nf < NFR; nf++) {
            int col = wn * TN_W + nf * 8 + (lane & 3) * 2;
            if (r < M)
                *(__half2*)(C + (size_t)r * N + col) =
                    __floats2half2_rn(acc[mi][nf][0], acc[mi][nf][1]);
            if (r + 8 < M)
                *(__half2*)(C + (size_t)(r + 8) * N + col) =
                    __floats2half2_rn(acc[mi][nf][2], acc[mi][nf][3]);
        }
    }
}

// ---------------- gather2: out = (sum m2[src]) * nd + b2 (fp32) ------------
__global__ __launch_bounds__(256) void gather2_kernel(
    const __half* __restrict__ m, float* __restrict__ agg,
    const float* __restrict__ bias, int N)
{
    constexpr int C = OUT_FEATS;
    int n    = (blockIdx.x * blockDim.x + threadIdx.x) >> 5;
    int lane = threadIdx.x & 31;
    if (n >= N) return;
    int beg = g_row_ptr[n];
    int cnt = g_degi_in[n];
    const int* __restrict__ ss = g_sorted_src + beg;

    float2 acc = make_float2(0.f, 0.f);
    int e = 0;
    for (; e + 4 <= cnt; e += 4) {
        int s0 = ss[e], s1 = ss[e + 1], s2 = ss[e + 2], s3 = ss[e + 3];
        uint32_t r0 = __ldg((const uint32_t*)(m + (size_t)s0 * C) + lane);
        uint32_t r1 = __ldg((const uint32_t*)(m + (size_t)s1 * C) + lane);
        uint32_t r2 = __ldg((const uint32_t*)(m + (size_t)s2 * C) + lane);
        uint32_t r3 = __ldg((const uint32_t*)(m + (size_t)s3 * C) + lane);
        float2 a;
        a = __half22float2(*(__half2*)&r0); acc.x += a.x; acc.y += a.y;
        a = __half22float2(*(__half2*)&r1); acc.x += a.x; acc.y += a.y;
        a = __half22float2(*(__half2*)&r2); acc.x += a.x; acc.y += a.y;
        a = __half22float2(*(__half2*)&r3); acc.x += a.x; acc.y += a.y;
    }
    for (; e < cnt; e++) {
        uint32_t r0 = __ldg((const uint32_t*)(m + (size_t)ss[e] * C) + lane);
        float2 a = __half22float2(*(__half2*)&r0);
        acc.x += a.x; acc.y += a.y;
    }
    float nd = g_nd[n];
    float2 bb = ((const float2*)bias)[lane];
    acc.x = acc.x * nd + bb.x; acc.y = acc.y * nd + bb.y;
    ((float2*)(agg + (size_t)n * C))[lane] = acc;
}

// ---------------- launch ---------------------------------------------------
extern "C" void kernel_launch(void* const* d_in, const int* in_sizes, int n_in,
                              void* d_out, int out_size) {
    const float* x  = (const float*)d_in[0];
    const void*  src = d_in[1];
    const void*  dst = d_in[2];
    const float* W1 = (const float*)d_in[3];
    const float* b1 = (const float*)d_in[4];
    const float* W2 = (const float*)d_in[5];
    const float* b2 = (const float*)d_in[6];
    float* out = (float*)d_out;

    int N = in_sizes[0] / IN_FEATS;   // 50000
    int E = in_sizes[1];              // 800000
    int nb = (N + SCAN_BLK - 1) / SCAN_BLK;
    int G1 = (N + 127) / 128;

    void *p_dego, *p_degi, *p_agg1, *p_m1, *p_m2, *p_ns;
    void *p_w1hi, *p_w1lo, *p_w2hi, *p_w2lo;
    cudaGetSymbolAddress(&p_dego, g_degi_out);
    cudaGetSymbolAddress(&p_degi, g_degi_in);
    cudaGetSymbolAddress(&p_agg1, g_agg1);
    cudaGetSymbolAddress(&p_m1,   g_m1);
    cudaGetSymbolAddress(&p_m2,   g_m2);
    cudaGetSymbolAddress(&p_ns,   g_ns);
    cudaGetSymbolAddress(&p_w1hi, g_w1hi);
    cudaGetSymbolAddress(&p_w1lo, g_w1lo);
    cudaGetSymbolAddress(&p_w2hi, g_w2hi);
    cudaGetSymbolAddress(&p_w2lo, g_w2lo);

    // smem: W chunk (hi+lo) + A chunk (hi+lo)
    constexpr int SMEM1 = 2 * HIDDEN * 72 * 2 + 2 * 128 * 72 * 2;       // 73728
    constexpr int SMEM2 = 2 * OUT_FEATS * 72 * 2 + 2 * 128 * 72 * 2;    // 55296
    cudaFuncSetAttribute(gemm1_deg_kernel,
                         cudaFuncAttributeMaxDynamicSharedMemorySize, SMEM1);
    cudaFuncSetAttribute(gemm2_kernel,
                         cudaFuncAttributeMaxDynamicSharedMemorySize, SMEM2);

    cudaMemsetAsync(p_dego, 0, (size_t)N * sizeof(int));
    cudaMemsetAsync(p_degi, 0, (size_t)N * sizeof(int));

    detect_i64_kernel<<<1, 1>>>((const unsigned int*)src, E);

    wprep_kernel<IN_FEATS, HIDDEN><<<(IN_FEATS * HIDDEN + 255) / 256, 256>>>(
        W1, (__nv_bfloat16*)p_w1hi, (__nv_bfloat16*)p_w1lo);
    wprep_kernel<HIDDEN, OUT_FEATS><<<(HIDDEN * OUT_FEATS + 255) / 256, 256>>>(
        W2, (__nv_bfloat16*)p_w2hi, (__nv_bfloat16*)p_w2lo);

    // MEGA: gemm1 (m1 = x @ W1, no ns) + degree counting overlapped
    gemm1_deg_kernel<<<G1 + DEG_BLOCKS, 256, SMEM1>>>(
        x, (const __nv_bfloat16*)p_w1hi, (const __nv_bfloat16*)p_w1lo,
        (__half*)p_m1, N, G1, src, dst, E);

    scan_block_sums<<<nb, SCAN_BLK>>>(N);
    scan_partials<<<1, SCAN_BLK>>>(nb);
    scan_final<<<nb, SCAN_BLK>>>(N);          // row_ptr + norms + cursor=0
    fill_csr_kernel<<<(E / 4 + 255) / 256, 256>>>(src, dst, E);

    // agg1 = (sum ns[s]*m1[s]) * nd + b1
    gather1_kernel<<<(N * 32 + 255) / 256, 256>>>(
        (const __half*)p_m1, (float*)p_agg1, b1, N);

    // m2 = (relu(agg1) * ns) @ W2  -> fp16
    gemm2_kernel<<<G1, 256, SMEM2>>>(
        (const float*)p_agg1, (const __nv_bfloat16*)p_w2hi, (const __nv_bfloat16*)p_w2lo,
        (__half*)p_m2, (const float*)p_ns, N);

    // out = (sum m2[src]) * nd + b2
    gather2_kernel<<<(N * 32 + 255) / 256, 256>>>(
        (const __half*)p_m2, out, b2, N);
}

// round 15
// speedup vs baseline: 1.2848x; 1.0437x over previous
#include <cuda_runtime.h>
#include <cuda_bf16.h>
#include <cuda_fp16.h>
#include <math.h>
#include <cstdint>

#define IN_FEATS 256
#define HIDDEN   128
#define OUT_FEATS 64
#define MAX_NODES 50048
#define MAX_EDGES 800000
#define SCAN_BLK  256
#define DEG_BLOCKS 112

// ---------------- scratch (static device globals) --------------------------
__device__ int   g_degi_out[MAX_NODES];
__device__ int   g_degi_in[MAX_NODES];
__device__ float g_ns[MAX_NODES];
__device__ float g_nd[MAX_NODES];
__device__ int   g_row_ptr[MAX_NODES];
__device__ int   g_cursor[MAX_NODES];
__device__ int   g_sorted_src[MAX_EDGES];
__device__ int   g_bsum[(MAX_NODES + SCAN_BLK - 1) / SCAN_BLK];
__device__ int   g_bpre[(MAX_NODES + SCAN_BLK - 1) / SCAN_BLK];
__device__ __align__(16) __half g_m1[(size_t)MAX_NODES * HIDDEN];
__device__ float g_agg1[(size_t)MAX_NODES * HIDDEN];
__device__ __align__(16) __half g_m2[(size_t)MAX_NODES * OUT_FEATS];
// W images, CHUNKED layout: [chunk][N][72] bf16 (chunk = 64 K-cols + 8 pad)
__device__ __align__(16) __nv_bfloat16 g_w1hi[(IN_FEATS / 64) * HIDDEN * 72];
__device__ __align__(16) __nv_bfloat16 g_w1lo[(IN_FEATS / 64) * HIDDEN * 72];
__device__ __align__(16) __nv_bfloat16 g_w2hi[(HIDDEN / 64) * OUT_FEATS * 72];
__device__ __align__(16) __nv_bfloat16 g_w2lo[(HIDDEN / 64) * OUT_FEATS * 72];
__device__ int   g_is64;

// ---------------- PTX helpers ----------------------------------------------
__device__ __forceinline__ uint32_t smem_u32(const void* p) {
    uint32_t a;
    asm("{ .reg .u64 t; cvta.to.shared.u64 t, %1; cvt.u32.u64 %0, t; }" : "=r"(a) : "l"(p));
    return a;
}

#define LDM_X4(r, a) \
    asm volatile("ldmatrix.sync.aligned.m8n8.x4.shared.b16 {%0,%1,%2,%3}, [%4];" \
        : "=r"((r)[0]), "=r"((r)[1]), "=r"((r)[2]), "=r"((r)[3]) : "r"(a))

#define MMA_BF16(d, a, b) \
    asm volatile("mma.sync.aligned.m16n8k16.row.col.f32.bf16.bf16.f32 " \
        "{%0,%1,%2,%3}, {%4,%5,%6,%7}, {%8,%9}, {%0,%1,%2,%3};" \
        : "+f"((d)[0]), "+f"((d)[1]), "+f"((d)[2]), "+f"((d)[3]) \
        : "r"((a)[0]), "r"((a)[1]), "r"((a)[2]), "r"((a)[3]), \
          "r"((b)[0]), "r"((b)[1]))

__device__ __forceinline__ void split_bf16(float v, unsigned short& h, unsigned short& l) {
    __nv_bfloat16 hb = __float2bfloat16(v);
    __nv_bfloat16 lb = __float2bfloat16(v - __bfloat162float(hb));
    h = *(unsigned short*)&hb;
    l = *(unsigned short*)&lb;
}

// ---------------- index dtype detector ------------------------------------
__global__ void detect_i64_kernel(const unsigned int* __restrict__ words, int E) {
    int is64 = 1;
    int nchk = E < 32 ? E : 32;
    for (int i = 0; i < nchk; i++) {
        if (words[2 * i + 1] != 0u) { is64 = 0; break; }
    }
    g_is64 = is64;
}

__device__ __forceinline__ int load_idx(const void* p, int i) {
    if (g_is64) return (int)((const long long*)p)[i];
    return ((const int*)p)[i];
}

// ---------------- exclusive scan of g_degi_in -> g_row_ptr -----------------
__global__ void scan_block_sums(int N) {
    __shared__ int sm[SCAN_BLK];
    int i = blockIdx.x * SCAN_BLK + threadIdx.x;
    int v = (i < N) ? g_degi_in[i] : 0;
    sm[threadIdx.x] = v;
    __syncthreads();
    for (int s = SCAN_BLK / 2; s > 0; s >>= 1) {
        if (threadIdx.x < s) sm[threadIdx.x] += sm[threadIdx.x + s];
        __syncthreads();
    }
    if (threadIdx.x == 0) g_bsum[blockIdx.x] = sm[0];
}

__global__ void scan_partials(int nb) {
    __shared__ int sm[SCAN_BLK];
    int v = (threadIdx.x < nb) ? g_bsum[threadIdx.x] : 0;
    sm[threadIdx.x] = v;
    __syncthreads();
    for (int off = 1; off < SCAN_BLK; off <<= 1) {
        int t = (threadIdx.x >= off) ? sm[threadIdx.x - off] : 0;
        __syncthreads();
        sm[threadIdx.x] += t;
        __syncthreads();
    }
    if (threadIdx.x < nb) g_bpre[threadIdx.x] = sm[threadIdx.x] - v;
}

// scan_final also computes norms and zeroes the cursor (fused)
__global__ void scan_final(int N) {
    __shared__ int sm[SCAN_BLK];
    int i = blockIdx.x * SCAN_BLK + threadIdx.x;
    int v = (i < N) ? g_degi_in[i] : 0;
    sm[threadIdx.x] = v;
    __syncthreads();
    for (int off = 1; off < SCAN_BLK; off <<= 1) {
        int t = (threadIdx.x >= off) ? sm[threadIdx.x - off] : 0;
        __syncthreads();
        sm[threadIdx.x] += t;
        __syncthreads();
    }
    if (i < N) {
        g_row_ptr[i] = g_bpre[blockIdx.x] + sm[threadIdx.x] - v;
        g_cursor[i] = 0;
        g_ns[i] = rsqrtf(fmaxf((float)g_degi_out[i], 1.0f));
        g_nd[i] = rsqrtf(fmaxf((float)v, 1.0f));
    }
}

// ---------------- counting-sort fill (4 edges/thread) ----------------------
__global__ void fill_csr_kernel(const void* __restrict__ src, const void* __restrict__ dst, int E) {
    int e0 = (blockIdx.x * blockDim.x + threadIdx.x) * 4;
    int s[4], d[4];
    #pragma unroll
    for (int i = 0; i < 4; i++) {
        int e = e0 + i;
        if (e < E) { s[i] = load_idx(src, e); d[i] = load_idx(dst, e); }
        else { s[i] = -1; d[i] = -1; }
    }
    #pragma unroll
    for (int i = 0; i < 4; i++) {
        if (s[i] >= 0) {
            int pos = g_row_ptr[d[i]] + atomicAdd(&g_cursor[d[i]], 1);
            g_sorted_src[pos] = s[i];
        }
    }
}

// ---------------- W prep: fp32 W[K,N] -> chunked bf16 hi/lo [chunk][N][72] -
template <int K, int N>
__global__ void wprep_kernel(const float* __restrict__ W,
                             __nv_bfloat16* __restrict__ hi,
                             __nv_bfloat16* __restrict__ lo) {
    int idx = blockIdx.x * blockDim.x + threadIdx.x;
    if (idx >= K * N) return;
    int n = idx / K;
    int k = idx - n * K;
    float v = W[(size_t)k * N + n];
    unsigned short h, l;
    split_bf16(v, h, l);
    int c = k >> 6, kc = k & 63;
    size_t off = ((size_t)c * N + n) * 72 + kc;
    hi[off] = *(__nv_bfloat16*)&h;
    lo[off] = *(__nv_bfloat16*)&l;
}

// ---------------- MEGA: gemm1 (m1 = x @ W1, unscaled) + degree counting ----
// 64-row M tiles (32 accum regs/thread -> >=2 CTAs/SM). Warps: 4m x 2n.
__global__ __launch_bounds__(256, 2) void gemm1_deg_kernel(
    const float* __restrict__ A,
    const __nv_bfloat16* __restrict__ Whi, const __nv_bfloat16* __restrict__ Wlo,
    __half* __restrict__ C, int M, int G1,
    const void* __restrict__ src, const void* __restrict__ dst, int E)
{
    constexpr int N = HIDDEN, KTOT = IN_FEATS;
    constexpr int BM = 64, BK = 64, BKP = 72;
    constexpr int TN_W = N / 2;          // 64 cols per n-warp
    constexpr int NFR = TN_W / 8;        // 8
    constexpr int WCH = N * BKP;         // 9216

    const int tid = threadIdx.x;

    // ---- degree-counting role ----
    if (blockIdx.x >= G1) {
        int b = blockIdx.x - G1;
        for (int e = b * 256 + tid; e < E; e += DEG_BLOCKS * 256) {
            int s = load_idx(src, e);
            int d = load_idx(dst, e);
            atomicAdd(&g_degi_out[s], 1);
            atomicAdd(&g_degi_in[d], 1);
        }
        return;
    }

    // ---- GEMM role ----
    extern __shared__ __nv_bfloat16 smbuf[];
    __nv_bfloat16* Wh = smbuf;                     // [N][72]
    __nv_bfloat16* Wl = smbuf + WCH;
    __nv_bfloat16* Ah = smbuf + 2 * (size_t)WCH;   // [64][72]
    __nv_bfloat16* Al = Ah + BM * BKP;

    const int lane = tid & 31, wid = tid >> 5;
    const int wm = wid & 3, wn = wid >> 2;
    const int row0 = blockIdx.x * BM;

    float acc[NFR][4] = {};

    const int a_row = (lane & 7) + ((lane >> 3) & 1) * 8;
    const int a_col = (lane >> 4) * 8;
    const int b_row = (lane & 7) + (lane >> 4) * 8;
    const int b_col = ((lane >> 3) & 1) * 8;

    for (int c = 0; c < KTOT / BK; c++) {
        __syncthreads();
        // stream this chunk's W slice into smem
        {
            const float4* s1 = (const float4*)(Whi + (size_t)c * WCH);
            const float4* s2 = (const float4*)(Wlo + (size_t)c * WCH);
            float4* d1 = (float4*)Wh;
            float4* d2 = (float4*)Wl;
            #pragma unroll
            for (int i = tid; i < WCH / 8; i += 256) { d1[i] = s1[i]; d2[i] = s2[i]; }
        }
        // load + convert A chunk: 64 rows x 64 cols fp32 -> bf16 hi/lo
        #pragma unroll
        for (int l = 0; l < 4; l++) {
            int idx = tid + l * 256;
            int m = idx >> 4, k4 = idx & 15;
            int gm = row0 + m;
            float4 v = make_float4(0.f, 0.f, 0.f, 0.f);
            if (gm < M)
                v = *(const float4*)(A + (size_t)gm * KTOT + c * BK + k4 * 4);
            ushort4 h4, l4;
            split_bf16(v.x, h4.x, l4.x);
            split_bf16(v.y, h4.y, l4.y);
            split_bf16(v.z, h4.z, l4.z);
            split_bf16(v.w, h4.w, l4.w);
            *(ushort4*)(Ah + m * BKP + k4 * 4) = h4;
            *(ushort4*)(Al + m * BKP + k4 * 4) = l4;
        }
        __syncthreads();

        #pragma unroll
        for (int k16 = 0; k16 < BK / 16; k16++) {
            int kc = k16 * 16;
            uint32_t ah[4], al[4];
            int ar = wm * 16 + a_row;
            LDM_X4(ah, smem_u32(Ah + ar * BKP + kc + a_col));
            LDM_X4(al, smem_u32(Al + ar * BKP + kc + a_col));
            #pragma unroll
            for (int ng = 0; ng < NFR / 2; ng++) {
                int n0 = wn * TN_W + ng * 16;
                uint32_t bh[4], bl[4];
                LDM_X4(bh, smem_u32(Wh + (n0 + b_row) * BKP + kc + b_col));
                LDM_X4(bl, smem_u32(Wl + (n0 + b_row) * BKP + kc + b_col));
                MMA_BF16(acc[2 * ng],     ah, (bh + 0));
                MMA_BF16(acc[2 * ng + 1], ah, (bh + 2));
                MMA_BF16(acc[2 * ng],     ah, (bl + 0));
                MMA_BF16(acc[2 * ng + 1], ah, (bl + 2));
                MMA_BF16(acc[2 * ng],     al, (bh + 0));
                MMA_BF16(acc[2 * ng + 1], al, (bh + 2));
            }
        }
    }

    {
        int r = row0 + wm * 16 + (lane >> 2);
        #pragma unroll
        for (int nf = 0; nf < NFR; nf++) {
            int col = wn * TN_W + nf * 8 + (lane & 3) * 2;
            if (r < M)
                *(__half2*)(C + (size_t)r * N + col) =
                    __floats2half2_rn(acc[nf][0], acc[nf][1]);
            if (r + 8 < M)
                *(__half2*)(C + (size_t)(r + 8) * N + col) =
                    __floats2half2_rn(acc[nf][2], acc[nf][3]);
        }
    }
}

// ---------------- gather1: agg1 = (sum ns[s]*m1[s]) * nd + b1 (fp32) -------
__global__ __launch_bounds__(256) void gather1_kernel(
    const __half* __restrict__ m, float* __restrict__ agg,
    const float* __restrict__ bias, int N)
{
    constexpr int C = HIDDEN;
    int n    = (blockIdx.x * blockDim.x + threadIdx.x) >> 5;
    int lane = threadIdx.x & 31;
    if (n >= N) return;
    int beg = g_row_ptr[n];
    int cnt = g_degi_in[n];
    const int* __restrict__ ss = g_sorted_src + beg;

    float4 acc = make_float4(0.f, 0.f, 0.f, 0.f);
    int e = 0;
    for (; e + 4 <= cnt; e += 4) {
        int s0 = ss[e], s1 = ss[e + 1], s2 = ss[e + 2], s3 = ss[e + 3];
        float n0 = __ldg(&g_ns[s0]), n1 = __ldg(&g_ns[s1]);
        float n2 = __ldg(&g_ns[s2]), n3 = __ldg(&g_ns[s3]);
        uint2 r0 = __ldg((const uint2*)(m + (size_t)s0 * C) + lane);
        uint2 r1 = __ldg((const uint2*)(m + (size_t)s1 * C) + lane);
        uint2 r2 = __ldg((const uint2*)(m + (size_t)s2 * C) + lane);
        uint2 r3 = __ldg((const uint2*)(m + (size_t)s3 * C) + lane);
        float2 a, b;
        a = __half22float2(*(__half2*)&r0.x); b = __half22float2(*(__half2*)&r0.y);
        acc.x = fmaf(a.x, n0, acc.x); acc.y = fmaf(a.y, n0, acc.y);
        acc.z = fmaf(b.x, n0, acc.z); acc.w = fmaf(b.y, n0, acc.w);
        a = __half22float2(*(__half2*)&r1.x); b = __half22float2(*(__half2*)&r1.y);
        acc.x = fmaf(a.x, n1, acc.x); acc.y = fmaf(a.y, n1, acc.y);
        acc.z = fmaf(b.x, n1, acc.z); acc.w = fmaf(b.y, n1, acc.w);
        a = __half22float2(*(__half2*)&r2.x); b = __half22float2(*(__half2*)&r2.y);
        acc.x = fmaf(a.x, n2, acc.x); acc.y = fmaf(a.y, n2, acc.y);
        acc.z = fmaf(b.x, n2, acc.z); acc.w = fmaf(b.y, n2, acc.w);
        a = __half22float2(*(__half2*)&r3.x); b = __half22float2(*(__half2*)&r3.y);
        acc.x = fmaf(a.x, n3, acc.x); acc.y = fmaf(a.y, n3, acc.y);
        acc.z = fmaf(b.x, n3, acc.z); acc.w = fmaf(b.y, n3, acc.w);
    }
    for (; e < cnt; e++) {
        int s0 = ss[e];
        float n0 = __ldg(&g_ns[s0]);
        uint2 r0 = __ldg((const uint2*)(m + (size_t)s0 * C) + lane);
        float2 a = __half22float2(*(__half2*)&r0.x);
        float2 b = __half22float2(*(__half2*)&r0.y);
        acc.x = fmaf(a.x, n0, acc.x); acc.y = fmaf(a.y, n0, acc.y);
        acc.z = fmaf(b.x, n0, acc.z); acc.w = fmaf(b.y, n0, acc.w);
    }
    float nd = g_nd[n];
    float4 bb = ((const float4*)bias)[lane];
    acc.x = acc.x * nd + bb.x; acc.y = acc.y * nd + bb.y;
    acc.z = acc.z * nd + bb.z; acc.w = acc.w * nd + bb.w;
    ((float4*)(agg + (size_t)n * C))[lane] = acc;
}

// ---------------- GEMM2: m2(fp16) = (relu(agg1)*ns) @ W2 -------------------
// 64-row M tiles. Warps: 4m x 2n (32 cols each). 16 accum regs/thread.
__global__ __launch_bounds__(256, 2) void gemm2_kernel(
    const float* __restrict__ A,
    const __nv_bfloat16* __restrict__ Whi, const __nv_bfloat16* __restrict__ Wlo,
    __half* __restrict__ C, const float* __restrict__ ns, int M)
{
    constexpr int N = OUT_FEATS, KTOT = HIDDEN;
    constexpr int BM = 64, BK = 64, BKP = 72;
    constexpr int TN_W = N / 2;          // 32
    constexpr int NFR = TN_W / 8;        // 4
    constexpr int WCH = N * BKP;         // 4608

    extern __shared__ __nv_bfloat16 smbuf[];
    __nv_bfloat16* Wh = smbuf;
    __nv_bfloat16* Wl = smbuf + WCH;
    __nv_bfloat16* Ah = smbuf + 2 * (size_t)WCH;
    __nv_bfloat16* Al = Ah + BM * BKP;

    const int tid = threadIdx.x, lane = tid & 31, wid = tid >> 5;
    const int wm = wid & 3, wn = wid >> 2;
    const int row0 = blockIdx.x * BM;

    float acc[NFR][4] = {};

    const int a_row = (lane & 7) + ((lane >> 3) & 1) * 8;
    const int a_col = (lane >> 4) * 8;
    const int b_row = (lane & 7) + (lane >> 4) * 8;
    const int b_col = ((lane >> 3) & 1) * 8;

    for (int c = 0; c < KTOT / BK; c++) {
        __syncthreads();
        {
            const float4* s1 = (const float4*)(Whi + (size_t)c * WCH);
            const float4* s2 = (const float4*)(Wlo + (size_t)c * WCH);
            float4* d1 = (float4*)Wh;
            float4* d2 = (float4*)Wl;
            #pragma unroll
            for (int i = tid; i < WCH / 8; i += 256) { d1[i] = s1[i]; d2[i] = s2[i]; }
        }
        #pragma unroll
        for (int l = 0; l < 4; l++) {
            int idx = tid + l * 256;
            int m = idx >> 4, k4 = idx & 15;
            int gm = row0 + m;
            float4 v = make_float4(0.f, 0.f, 0.f, 0.f);
            if (gm < M) {
                v = *(const float4*)(A + (size_t)gm * KTOT + c * BK + k4 * 4);
                float s = ns[gm];
                v.x = fmaxf(v.x, 0.f) * s; v.y = fmaxf(v.y, 0.f) * s;
                v.z = fmaxf(v.z, 0.f) * s; v.w = fmaxf(v.w, 0.f) * s;
            }
            ushort4 h4, l4;
            split_bf16(v.x, h4.x, l4.x);
            split_bf16(v.y, h4.y, l4.y);
            split_bf16(v.z, h4.z, l4.z);
            split_bf16(v.w, h4.w, l4.w);
            *(ushort4*)(Ah + m * BKP + k4 * 4) = h4;
            *(ushort4*)(Al + m * BKP + k4 * 4) = l4;
        }
        __syncthreads();

        #pragma unroll
        for (int k16 = 0; k16 < BK / 16; k16++) {
            int kc = k16 * 16;
            uint32_t ah[4], al[4];
            int ar = wm * 16 + a_row;
            LDM_X4(ah, smem_u32(Ah + ar * BKP + kc + a_col));
            LDM_X4(al, smem_u32(Al + ar * BKP + kc + a_col));
            #pragma unroll
            for (int ng = 0; ng < NFR / 2; ng++) {
                int n0 = wn * TN_W + ng * 16;
                uint32_t bh[4], bl[4];
                LDM_X4(bh, smem_u32(Wh + (n0 + b_row) * BKP + kc + b_col));
                LDM_X4(bl, smem_u32(Wl + (n0 + b_row) * BKP + kc + b_col));
                MMA_BF16(acc[2 * ng],     ah, (bh + 0));
                MMA_BF16(acc[2 * ng + 1], ah, (bh + 2));
                MMA_BF16(acc[2 * ng],     ah, (bl + 0));
                MMA_BF16(acc[2 * ng + 1], ah, (bl + 2));
                MMA_BF16(acc[2 * ng],     al, (bh + 0));
                MMA_BF16(acc[2 * ng + 1], al, (bh + 2));
            }
        }
    }

    {
        int r = row0 + wm * 16 + (lane >> 2);
        #pragma unroll
        for (int nf = 0; nf < NFR; nf++) {
            int col = wn * TN_W + nf * 8 + (lane & 3) * 2;
            if (r < M)
                *(__half2*)(C + (size_t)r * N + col) =
                    __floats2half2_rn(acc[nf][0], acc[nf][1]);
            if (r + 8 < M)
                *(__half2*)(C + (size_t)(r + 8) * N + col) =
                    __floats2half2_rn(acc[nf][2], acc[nf][3]);
        }
    }
}

// ---------------- gather2: out = (sum m2[src]) * nd + b2 (fp32) ------------
__global__ __launch_bounds__(256) void gather2_kernel(
    const __half* __restrict__ m, float* __restrict__ agg,
    const float* __restrict__ bias, int N)
{
    constexpr int C = OUT_FEATS;
    int n    = (blockIdx.x * blockDim.x + threadIdx.x) >> 5;
    int lane = threadIdx.x & 31;
    if (n >= N) return;
    int beg = g_row_ptr[n];
    int cnt = g_degi_in[n];
    const int* __restrict__ ss = g_sorted_src + beg;

    float2 acc = make_float2(0.f, 0.f);
    int e = 0;
    for (; e + 4 <= cnt; e += 4) {
        int s0 = ss[e], s1 = ss[e + 1], s2 = ss[e + 2], s3 = ss[e + 3];
        uint32_t r0 = __ldg((const uint32_t*)(m + (size_t)s0 * C) + lane);
        uint32_t r1 = __ldg((const uint32_t*)(m + (size_t)s1 * C) + lane);
        uint32_t r2 = __ldg((const uint32_t*)(m + (size_t)s2 * C) + lane);
        uint32_t r3 = __ldg((const uint32_t*)(m + (size_t)s3 * C) + lane);
        float2 a;
        a = __half22float2(*(__half2*)&r0); acc.x += a.x; acc.y += a.y;
        a = __half22float2(*(__half2*)&r1); acc.x += a.x; acc.y += a.y;
        a = __half22float2(*(__half2*)&r2); acc.x += a.x; acc.y += a.y;
        a = __half22float2(*(__half2*)&r3); acc.x += a.x; acc.y += a.y;
    }
    for (; e < cnt; e++) {
        uint32_t r0 = __ldg((const uint32_t*)(m + (size_t)ss[e] * C) + lane);
        float2 a = __half22float2(*(__half2*)&r0);
        acc.x += a.x; acc.y += a.y;
    }
    float nd = g_nd[n];
    float2 bb = ((const float2*)bias)[lane];
    acc.x = acc.x * nd + bb.x; acc.y = acc.y * nd + bb.y;
    ((float2*)(agg + (size_t)n * C))[lane] = acc;
}

// ---------------- launch ---------------------------------------------------
extern "C" void kernel_launch(void* const* d_in, const int* in_sizes, int n_in,
                              void* d_out, int out_size) {
    const float* x  = (const float*)d_in[0];
    const void*  src = d_in[1];
    const void*  dst = d_in[2];
    const float* W1 = (const float*)d_in[3];
    const float* b1 = (const float*)d_in[4];
    const float* W2 = (const float*)d_in[5];
    const float* b2 = (const float*)d_in[6];
    float* out = (float*)d_out;

    int N = in_sizes[0] / IN_FEATS;   // 50000
    int E = in_sizes[1];              // 800000
    int nb = (N + SCAN_BLK - 1) / SCAN_BLK;
    int G1 = (N + 63) / 64;

    void *p_dego, *p_degi, *p_agg1, *p_m1, *p_m2, *p_ns;
    void *p_w1hi, *p_w1lo, *p_w2hi, *p_w2lo;
    cudaGetSymbolAddress(&p_dego, g_degi_out);
    cudaGetSymbolAddress(&p_degi, g_degi_in);
    cudaGetSymbolAddress(&p_agg1, g_agg1);
    cudaGetSymbolAddress(&p_m1,   g_m1);
    cudaGetSymbolAddress(&p_m2,   g_m2);
    cudaGetSymbolAddress(&p_ns,   g_ns);
    cudaGetSymbolAddress(&p_w1hi, g_w1hi);
    cudaGetSymbolAddress(&p_w1lo, g_w1lo);
    cudaGetSymbolAddress(&p_w2hi, g_w2hi);
    cudaGetSymbolAddress(&p_w2lo, g_w2lo);

    // smem: W chunk (hi+lo) + A chunk (hi+lo), 64-row tiles
    constexpr int SMEM1 = 2 * HIDDEN * 72 * 2 + 2 * 64 * 72 * 2;       // 55296
    constexpr int SMEM2 = 2 * OUT_FEATS * 72 * 2 + 2 * 64 * 72 * 2;    // 36864
    cudaFuncSetAttribute(gemm1_deg_kernel,
                         cudaFuncAttributeMaxDynamicSharedMemorySize, SMEM1);
    cudaFuncSetAttribute(gemm2_kernel,
                         cudaFuncAttributeMaxDynamicSharedMemorySize, SMEM2);

    cudaMemsetAsync(p_dego, 0, (size_t)N * sizeof(int));
    cudaMemsetAsync(p_degi, 0, (size_t)N * sizeof(int));

    detect_i64_kernel<<<1, 1>>>((const unsigned int*)src, E);

    wprep_kernel<IN_FEATS, HIDDEN><<<(IN_FEATS * HIDDEN + 255) / 256, 256>>>(
        W1, (__nv_bfloat16*)p_w1hi, (__nv_bfloat16*)p_w1lo);
    wprep_kernel<HIDDEN, OUT_FEATS><<<(HIDDEN * OUT_FEATS + 255) / 256, 256>>>(
        W2, (__nv_bfloat16*)p_w2hi, (__nv_bfloat16*)p_w2lo);

    // MEGA: gemm1 (m1 = x @ W1, no ns) + degree counting overlapped
    gemm1_deg_kernel<<<G1 + DEG_BLOCKS, 256, SMEM1>>>(
        x, (const __nv_bfloat16*)p_w1hi, (const __nv_bfloat16*)p_w1lo,
        (__half*)p_m1, N, G1, src, dst, E);

    scan_block_sums<<<nb, SCAN_BLK>>>(N);
    scan_partials<<<1, SCAN_BLK>>>(nb);
    scan_final<<<nb, SCAN_BLK>>>(N);          // row_ptr + norms + cursor=0
    fill_csr_kernel<<<(E / 4 + 255) / 256, 256>>>(src, dst, E);

    // agg1 = (sum ns[s]*m1[s]) * nd + b1
    gather1_kernel<<<(N * 32 + 255) / 256, 256>>>(
        (const __half*)p_m1, (float*)p_agg1, b1, N);

    // m2 = (relu(agg1) * ns) @ W2  -> fp16
    gemm2_kernel<<<(N + 63) / 64, 256, SMEM2>>>(
        (const float*)p_agg1, (const __nv_bfloat16*)p_w2hi, (const __nv_bfloat16*)p_w2lo,
        (__half*)p_m2, (const float*)p_ns, N);

    // out = (sum m2[src]) * nd + b2
    gather2_kernel<<<(N * 32 + 255) / 256, 256>>>(
        (const __half*)p_m2, out, b2, N);
}